// round 12
// baseline (speedup 1.0000x reference)
#include <cuda_runtime.h>
#include <cuda_bf16.h>
#include <cuda_fp16.h>
#include <math.h>
#include <float.h>
#include <stdint.h>

#define BATCH 2
#define NTOK  8000
#define CDIM  512
#define NSR   1000
#define NHEADS 8
#define HD    64

__device__ float g_kv[BATCH * NSR * 2 * CDIM];
__device__ float g_o [BATCH * NTOK * CDIM];
__device__ __half g_xh [BATCH * NTOK * CDIM];
__device__ __half g_yh [BATCH * NTOK * CDIM];
__device__ __half g_yl [BATCH * NTOK * CDIM];
__device__ __half g_qh [BATCH * NTOK * CDIM];
__device__ __half g_kvh[BATCH * NSR * 2 * CDIM];
__device__ __half g_xrh[BATCH * NSR * CDIM];
__device__ __half g_xrl[BATCH * NSR * CDIM];
__device__ __half g_wqt [CDIM * CDIM];
__device__ __half g_wkvt[2 * CDIM * CDIM];
__device__ __half g_wpt [CDIM * CDIM];

// ---------------- ptx helpers ----------------
__device__ __forceinline__ void ldsm4(uint32_t& r0, uint32_t& r1, uint32_t& r2, uint32_t& r3,
                                      uint32_t addr)
{
    asm volatile("ldmatrix.sync.aligned.m8n8.x4.shared.b16 {%0,%1,%2,%3}, [%4];"
                 : "=r"(r0), "=r"(r1), "=r"(r2), "=r"(r3) : "r"(addr));
}
__device__ __forceinline__ void ldsm4t(uint32_t& r0, uint32_t& r1, uint32_t& r2, uint32_t& r3,
                                       uint32_t addr)
{
    asm volatile("ldmatrix.sync.aligned.m8n8.x4.trans.shared.b16 {%0,%1,%2,%3}, [%4];"
                 : "=r"(r0), "=r"(r1), "=r"(r2), "=r"(r3) : "r"(addr));
}
__device__ __forceinline__ void mma16816h(float* c, const uint32_t* a, const uint32_t* b)
{
    asm volatile("mma.sync.aligned.m16n8k16.row.col.f32.f16.f16.f32 "
                 "{%0,%1,%2,%3}, {%4,%5,%6,%7}, {%8,%9}, {%0,%1,%2,%3};"
                 : "+f"(c[0]), "+f"(c[1]), "+f"(c[2]), "+f"(c[3])
                 : "r"(a[0]), "r"(a[1]), "r"(a[2]), "r"(a[3]), "r"(b[0]), "r"(b[1]));
}
__device__ __forceinline__ uint32_t packh2(float a, float b) {
    __half2 t = __floats2half2_rn(a, b);
    return *(uint32_t*)&t;
}

// ---------------- convert fp32 -> fp16 ----------------
__global__ void __launch_bounds__(256) cvt_kernel(
    const float* __restrict__ s, __half* __restrict__ h, int n)
{
    int i = blockIdx.x * 256 + threadIdx.x;
    if (i < n) h[i] = __float2half(s[i]);
}

// ---------------- transpose ALL weights to fp16 [N][K] in one launch ----------------
__global__ void __launch_bounds__(256) wsplit_all_kernel(
    const float* __restrict__ Wq, const float* __restrict__ Wkv,
    const float* __restrict__ Wp,
    __half* __restrict__ qt, __half* __restrict__ kt, __half* __restrict__ pt)
{
    __shared__ float t[32][33];
    int tb = blockIdx.x;
    const float* W; __half* T; int N, nb, kb;
    if (tb < 256)      { W = Wq;  T = qt; N = 512;  int tt = tb;       nb = (tt & 15) * 32; kb = (tt >> 4) * 32; }
    else if (tb < 768) { W = Wkv; T = kt; N = 1024; int tt = tb - 256; nb = (tt & 31) * 32; kb = (tt >> 5) * 32; }
    else               { W = Wp;  T = pt; N = 512;  int tt = tb - 768; nb = (tt & 15) * 32; kb = (tt >> 4) * 32; }
    const int K = 512;
    int tx = threadIdx.x & 31, ty = threadIdx.x >> 5;
#pragma unroll
    for (int i = ty; i < 32; i += 8)
        t[i][tx] = W[(size_t)(kb + i) * N + nb + tx];
    __syncthreads();
#pragma unroll
    for (int i = ty; i < 32; i += 8)
        T[(size_t)(nb + i) * K + kb + tx] = __float2half(t[tx][i]);
}

// ---------------- conv3d depthwise (3,s2,p1) + bias + LN -> fp16 hi/lo ----------------
__global__ void __launch_bounds__(256) conv_ln_kernel(
    const float* __restrict__ x, const float* __restrict__ srw,
    const float* __restrict__ srb, const float* __restrict__ g,
    const float* __restrict__ beta,
    __half* __restrict__ xrh, __half* __restrict__ xrl)
{
    int bp = blockIdx.x;
    int b = bp / NSR, opos = bp % NSR;
    int od = opos / 100, oh = (opos / 10) % 10, ow = opos % 10;
    __shared__ float vals[CDIM];
    __shared__ float red[18];
    float loc[2];
#pragma unroll
    for (int ci = 0; ci < 2; ci++) {
        int c = threadIdx.x + ci * 256;
        float acc = srb[c];
#pragma unroll
        for (int kd = 0; kd < 3; kd++) {
            int id = od * 2 - 1 + kd;
            if ((unsigned)id >= 20u) continue;
#pragma unroll
            for (int kh = 0; kh < 3; kh++) {
                int ih = oh * 2 - 1 + kh;
                if ((unsigned)ih >= 20u) continue;
#pragma unroll
                for (int kw = 0; kw < 3; kw++) {
                    int iw = ow * 2 - 1 + kw;
                    if ((unsigned)iw >= 20u) continue;
                    acc += x[((size_t)b * NTOK + id * 400 + ih * 20 + iw) * CDIM + c] *
                           srw[c * 27 + kd * 9 + kh * 3 + kw];
                }
            }
        }
        vals[c] = acc; loc[ci] = acc;
    }
    float s = loc[0] + loc[1], sq = loc[0] * loc[0] + loc[1] * loc[1];
#pragma unroll
    for (int o2 = 16; o2 > 0; o2 >>= 1) {
        s  += __shfl_down_sync(0xffffffffu, s,  o2);
        sq += __shfl_down_sync(0xffffffffu, sq, o2);
    }
    int w = threadIdx.x >> 5;
    if ((threadIdx.x & 31) == 0) { red[w] = s; red[8 + w] = sq; }
    __syncthreads();
    if (threadIdx.x == 0) {
        float a = 0.f, b2 = 0.f;
        for (int i = 0; i < 8; i++) { a += red[i]; b2 += red[8 + i]; }
        red[16] = a; red[17] = b2;
    }
    __syncthreads();
    float mean = red[16] * (1.f / CDIM);
    float var  = red[17] * (1.f / CDIM) - mean * mean;
    float inv  = rsqrtf(var + 1e-6f);
#pragma unroll
    for (int ci = 0; ci < 2; ci++) {
        int c = threadIdx.x + ci * 256;
        float v = (vals[c] - mean) * inv * g[c] + beta[c];
        size_t idx = ((size_t)b * NSR + opos) * CDIM + c;
        __half hh = __float2half(v);
        xrh[idx] = hh;
        xrl[idx] = __float2half(v - __half2float(hh));
    }
}

#define SMS 40

// ---------------- fp16 2-term GEMM: C = (Ah+Al)[M,512] @ B[N,512]^T + bias ----------------
__global__ void __launch_bounds__(256) gemm2h_kernel(
    const __half* __restrict__ Ah, const __half* __restrict__ Al,
    const __half* __restrict__ B, const float* __restrict__ bias,
    float* __restrict__ C, __half* __restrict__ Ch, int M, int N)
{
    __shared__ __half sAh[128 * SMS], sAl[128 * SMS], sB[128 * SMS];

    int tid = threadIdx.x, wid = tid >> 5, lane = tid & 31;
    int wr = wid >> 2, wc = wid & 3;
    int rowBase = blockIdx.y * 128, colBase = blockIdx.x * 128;

    float acc[4][4][4];
#pragma unroll
    for (int i = 0; i < 4; i++)
#pragma unroll
        for (int j = 0; j < 4; j++)
#pragma unroll
            for (int k = 0; k < 4; k++) acc[i][j][k] = 0.f;

    uint32_t aBaseH = (uint32_t)__cvta_generic_to_shared(sAh);
    uint32_t aBaseL = (uint32_t)__cvta_generic_to_shared(sAl);
    uint32_t bBase  = (uint32_t)__cvta_generic_to_shared(sB);

    for (int k0 = 0; k0 < 512; k0 += 32) {
        __syncthreads();
#pragma unroll
        for (int it = 0; it < 2; it++) {
            int idx = tid + it * 256;
            int r = idx >> 2, c = idx & 3;
            int ar = rowBase + r; if (ar > M - 1) ar = M - 1;
            int br = colBase + r;
            size_t aoff = (size_t)ar * 512 + k0 + c * 8;
            size_t boff = (size_t)br * 512 + k0 + c * 8;
            int soff = r * SMS + c * 8;
            *(uint4*)&sAh[soff] = *(const uint4*)&Ah[aoff];
            *(uint4*)&sAl[soff] = *(const uint4*)&Al[aoff];
            *(uint4*)&sB [soff] = *(const uint4*)&B [boff];
        }
        __syncthreads();

#pragma unroll
        for (int ks = 0; ks < 32; ks += 16) {
            uint32_t aoffs = (uint32_t)(((wr * 64 + (lane & 15)) * SMS + ks + ((lane >> 4) << 3)) * 2);
            uint32_t boffs = (uint32_t)(((wc * 32 + ((lane >> 4) << 3) + (lane & 7)) * SMS + ks + (((lane >> 3) & 1) << 3)) * 2);

            uint32_t ah[4][4], al[4][4];
#pragma unroll
            for (int mf = 0; mf < 4; mf++) {
                uint32_t ao = aoffs + (uint32_t)(mf * 16 * SMS * 2);
                ldsm4(ah[mf][0], ah[mf][1], ah[mf][2], ah[mf][3], aBaseH + ao);
                ldsm4(al[mf][0], al[mf][1], al[mf][2], al[mf][3], aBaseL + ao);
            }
            uint32_t bh[4][2];
#pragma unroll
            for (int np = 0; np < 2; np++) {
                uint32_t bo = boffs + (uint32_t)(np * 16 * SMS * 2);
                ldsm4(bh[np * 2][0], bh[np * 2][1], bh[np * 2 + 1][0], bh[np * 2 + 1][1], bBase + bo);
            }
#pragma unroll
            for (int mf = 0; mf < 4; mf++)
#pragma unroll
                for (int nf = 0; nf < 4; nf++) {
                    mma16816h(acc[mf][nf], ah[mf], bh[nf]);
                    mma16816h(acc[mf][nf], al[mf], bh[nf]);
                }
        }
    }

#pragma unroll
    for (int mf = 0; mf < 4; mf++) {
#pragma unroll
        for (int nf = 0; nf < 4; nf++) {
            int row0 = rowBase + wr * 64 + mf * 16 + (lane >> 2);
            int col  = colBase + wc * 32 + nf * 8 + 2 * (lane & 3);
            float b0 = bias[col], b1 = bias[col + 1];
#pragma unroll
            for (int half = 0; half < 2; half++) {
                int row = row0 + half * 8;
                if (row < M) {
                    float v0 = acc[mf][nf][half * 2]     + b0;
                    float v1 = acc[mf][nf][half * 2 + 1] + b1;
                    size_t o0 = (size_t)row * N + col;
                    if (C) { C[o0] = v0; C[o0 + 1] = v1; }
                    if (Ch) {
                        Ch[o0]     = __float2half(v0);
                        Ch[o0 + 1] = __float2half(v1);
                    }
                }
            }
        }
    }
}

// ---------------- fp16 1-term GEMM: C = A[M,512] @ B[N,512]^T + bias -> fp16 ----------------
__global__ void __launch_bounds__(256) gemm1h_kernel(
    const __half* __restrict__ A, const __half* __restrict__ B,
    const float* __restrict__ bias, __half* __restrict__ Ch, int M, int N)
{
    __shared__ __half sA[128 * SMS], sB[128 * SMS];

    int tid = threadIdx.x, wid = tid >> 5, lane = tid & 31;
    int wr = wid >> 2, wc = wid & 3;
    int rowBase = blockIdx.y * 128, colBase = blockIdx.x * 128;

    float acc[4][4][4];
#pragma unroll
    for (int i = 0; i < 4; i++)
#pragma unroll
        for (int j = 0; j < 4; j++)
#pragma unroll
            for (int k = 0; k < 4; k++) acc[i][j][k] = 0.f;

    uint32_t aBase = (uint32_t)__cvta_generic_to_shared(sA);
    uint32_t bBase = (uint32_t)__cvta_generic_to_shared(sB);

    for (int k0 = 0; k0 < 512; k0 += 32) {
        __syncthreads();
#pragma unroll
        for (int it = 0; it < 2; it++) {
            int idx = tid + it * 256;
            int r = idx >> 2, c = idx & 3;
            int ar = rowBase + r; if (ar > M - 1) ar = M - 1;
            int br = colBase + r;
            size_t aoff = (size_t)ar * 512 + k0 + c * 8;
            size_t boff = (size_t)br * 512 + k0 + c * 8;
            int soff = r * SMS + c * 8;
            *(uint4*)&sA[soff] = *(const uint4*)&A[aoff];
            *(uint4*)&sB[soff] = *(const uint4*)&B[boff];
        }
        __syncthreads();

#pragma unroll
        for (int ks = 0; ks < 32; ks += 16) {
            uint32_t aoffs = (uint32_t)(((wr * 64 + (lane & 15)) * SMS + ks + ((lane >> 4) << 3)) * 2);
            uint32_t boffs = (uint32_t)(((wc * 32 + ((lane >> 4) << 3) + (lane & 7)) * SMS + ks + (((lane >> 3) & 1) << 3)) * 2);

            uint32_t a_[4][4];
#pragma unroll
            for (int mf = 0; mf < 4; mf++) {
                uint32_t ao = aoffs + (uint32_t)(mf * 16 * SMS * 2);
                ldsm4(a_[mf][0], a_[mf][1], a_[mf][2], a_[mf][3], aBase + ao);
            }
            uint32_t bh[4][2];
#pragma unroll
            for (int np = 0; np < 2; np++) {
                uint32_t bo = boffs + (uint32_t)(np * 16 * SMS * 2);
                ldsm4(bh[np * 2][0], bh[np * 2][1], bh[np * 2 + 1][0], bh[np * 2 + 1][1], bBase + bo);
            }
#pragma unroll
            for (int mf = 0; mf < 4; mf++)
#pragma unroll
                for (int nf = 0; nf < 4; nf++)
                    mma16816h(acc[mf][nf], a_[mf], bh[nf]);
        }
    }

#pragma unroll
    for (int mf = 0; mf < 4; mf++) {
#pragma unroll
        for (int nf = 0; nf < 4; nf++) {
            int row0 = rowBase + wr * 64 + mf * 16 + (lane >> 2);
            int col  = colBase + wc * 32 + nf * 8 + 2 * (lane & 3);
            float b0 = bias[col], b1 = bias[col + 1];
#pragma unroll
            for (int half = 0; half < 2; half++) {
                int row = row0 + half * 8;
                if (row < M) {
                    size_t o0 = (size_t)row * N + col;
                    Ch[o0]     = __float2half(acc[mf][nf][half * 2]     + b0);
                    Ch[o0 + 1] = __float2half(acc[mf][nf][half * 2 + 1] + b1);
                }
            }
        }
    }
}

// ---------------- flash attention: 128-query tile, 256 thr, all-fp16, base-2 softmax ----------------
#define AST 72
#define AT_SCALE 0.18033688f   // 0.125 * log2(e)
__global__ void __launch_bounds__(256) attn_mma_kernel(
    const __half* __restrict__ q, const __half* __restrict__ kvh,
    float* __restrict__ o)
{
    __shared__ __half sQ[128 * AST];
    __shared__ __half sK[64 * AST];
    __shared__ __half sV[64 * AST];

    int tid = threadIdx.x, wid = tid >> 5, lane = tid & 31;
    int bh = blockIdx.y, b = bh >> 3, h = bh & 7;
    int qbase = blockIdx.x * 128;
    size_t qrow0 = (size_t)b * NTOK;

    // load Q tile (128 rows, row-clamped for the tail block)
#pragma unroll
    for (int i = 0; i < 4; i++) {
        int idx = tid + i * 256;
        int r = idx >> 3, c = (idx & 7) << 3;
        int gr = qbase + r; if (gr > NTOK - 1) gr = NTOK - 1;
        *(uint4*)&sQ[r * AST + c] = *(const uint4*)&q[(qrow0 + gr) * CDIM + h * HD + c];
    }
    __syncthreads();

    uint32_t bQ = (uint32_t)__cvta_generic_to_shared(sQ);
    uint32_t bK = (uint32_t)__cvta_generic_to_shared(sK);
    uint32_t bV = (uint32_t)__cvta_generic_to_shared(sV);

    uint32_t qf[4][4];
    {
        uint32_t qrow = (uint32_t)(wid * 16 + (lane & 15));
#pragma unroll
        for (int kt = 0; kt < 4; kt++) {
            uint32_t off = (qrow * AST + kt * 16 + ((lane >> 4) << 3)) * 2;
            ldsm4(qf[kt][0], qf[kt][1], qf[kt][2], qf[kt][3], bQ + off);
        }
    }

    float acc[8][4];
#pragma unroll
    for (int i = 0; i < 8; i++)
#pragma unroll
        for (int j = 0; j < 4; j++) acc[i][j] = 0.f;
    float m0 = -FLT_MAX, m1 = -FLT_MAX, l0 = 0.f, l1 = 0.f;

    size_t kvoff = (size_t)b * NSR * 1024 + h * HD;
    int cbase = 2 * (lane & 3);

    for (int kb = 0; kb < NSR; kb += 64) {
        __syncthreads();
#pragma unroll
        for (int i = 0; i < 2; i++) {
            int idx = tid + i * 256;
            int r = idx >> 3, c = (idx & 7) << 3;
            int gm = kb + r;
            uint4 z = make_uint4(0u, 0u, 0u, 0u);
            uint4 a0 = z, a1 = z;
            if (gm < NSR) {
                size_t base = kvoff + (size_t)gm * 1024 + c;
                a0 = *(const uint4*)&kvh[base];
                a1 = *(const uint4*)&kvh[base + 512];
            }
            *(uint4*)&sK[r * AST + c] = a0;
            *(uint4*)&sV[r * AST + c] = a1;
        }
        __syncthreads();

        // S = Q K^T
        float s_[8][4];
#pragma unroll
        for (int i = 0; i < 8; i++)
#pragma unroll
            for (int j = 0; j < 4; j++) s_[i][j] = 0.f;

#pragma unroll
        for (int kt = 0; kt < 4; kt++) {
#pragma unroll
            for (int np = 0; np < 4; np++) {
                uint32_t brow = (uint32_t)(np * 16 + ((lane >> 4) << 3) + (lane & 7));
                uint32_t boff = (brow * AST + kt * 16 + (((lane >> 3) & 1) << 3)) * 2;
                uint32_t h0, h1, h2, h3;
                ldsm4(h0, h1, h2, h3, bK + boff);
                uint32_t fh0[2] = {h0, h1}, fh1[2] = {h2, h3};
                mma16816h(s_[np * 2],     qf[kt], fh0);
                mma16816h(s_[np * 2 + 1], qf[kt], fh1);
            }
        }

        // online softmax in base-2 (register, quad shuffles)
        int valid = NSR - kb; if (valid > 64) valid = 64;
        float rm0 = -FLT_MAX, rm1 = -FLT_MAX;
#pragma unroll
        for (int nt = 0; nt < 8; nt++) {
#pragma unroll
            for (int j = 0; j < 4; j++) s_[nt][j] *= AT_SCALE;
            rm0 = fmaxf(rm0, fmaxf(s_[nt][0], s_[nt][1]));
            rm1 = fmaxf(rm1, fmaxf(s_[nt][2], s_[nt][3]));
        }
        rm0 = fmaxf(rm0, __shfl_xor_sync(0xffffffffu, rm0, 1));
        rm0 = fmaxf(rm0, __shfl_xor_sync(0xffffffffu, rm0, 2));
        rm1 = fmaxf(rm1, __shfl_xor_sync(0xffffffffu, rm1, 1));
        rm1 = fmaxf(rm1, __shfl_xor_sync(0xffffffffu, rm1, 2));
        float nm0 = fmaxf(m0, rm0), nm1 = fmaxf(m1, rm1);
        float corr0 = exp2f(m0 - nm0), corr1 = exp2f(m1 - nm1);
        m0 = nm0; m1 = nm1;

        float sum0 = 0.f, sum1 = 0.f;
#pragma unroll
        for (int nt = 0; nt < 8; nt++) {
            int c0 = nt * 8 + cbase;
            float p0 = (c0     < valid) ? exp2f(s_[nt][0] - nm0) : 0.f;
            float p1 = (c0 + 1 < valid) ? exp2f(s_[nt][1] - nm0) : 0.f;
            float p2 = (c0     < valid) ? exp2f(s_[nt][2] - nm1) : 0.f;
            float p3 = (c0 + 1 < valid) ? exp2f(s_[nt][3] - nm1) : 0.f;
            sum0 += p0 + p1; sum1 += p2 + p3;
            s_[nt][0] = p0; s_[nt][1] = p1; s_[nt][2] = p2; s_[nt][3] = p3;
        }
        sum0 += __shfl_xor_sync(0xffffffffu, sum0, 1);
        sum0 += __shfl_xor_sync(0xffffffffu, sum0, 2);
        sum1 += __shfl_xor_sync(0xffffffffu, sum1, 1);
        sum1 += __shfl_xor_sync(0xffffffffu, sum1, 2);
        l0 = l0 * corr0 + sum0;
        l1 = l1 * corr1 + sum1;

#pragma unroll
        for (int nt = 0; nt < 8; nt++) {
            acc[nt][0] *= corr0; acc[nt][1] *= corr0;
            acc[nt][2] *= corr1; acc[nt][3] *= corr1;
        }

        // O += P V
#pragma unroll
        for (int kt = 0; kt < 4; kt++) {
            uint32_t ph[4];
#pragma unroll
            for (int q2 = 0; q2 < 2; q2++) {
                int nt = 2 * kt + q2;
                ph[q2 * 2]     = packh2(s_[nt][0], s_[nt][1]);
                ph[q2 * 2 + 1] = packh2(s_[nt][2], s_[nt][3]);
            }
            int l8 = lane >> 3, li = lane & 7;
#pragma unroll
            for (int np = 0; np < 4; np++) {
                uint32_t vrow = (uint32_t)(kt * 16 + ((l8 & 1) << 3) + li);
                uint32_t vcol = (uint32_t)(np * 16 + ((l8 >> 1) << 3));
                uint32_t voff = (vrow * AST + vcol) * 2;
                uint32_t h0, h1, h2, h3;
                ldsm4t(h0, h1, h2, h3, bV + voff);
                uint32_t fh0[2] = {h0, h1}, fh1[2] = {h2, h3};
                mma16816h(acc[np * 2],     ph, fh0);
                mma16816h(acc[np * 2 + 1], ph, fh1);
            }
        }
    }

    float inv0 = 1.f / l0, inv1 = 1.f / l1;
    int r0 = qbase + wid * 16 + (lane >> 2);
    size_t ob0 = (qrow0 + r0) * CDIM + h * HD;
    size_t ob1 = ob0 + (size_t)8 * CDIM;
    bool s0 = r0 < NTOK, s1 = (r0 + 8) < NTOK;
#pragma unroll
    for (int nt = 0; nt < 8; nt++) {
        int cc = nt * 8 + cbase;
        if (s0) {
            o[ob0 + cc]     = acc[nt][0] * inv0;
            o[ob0 + cc + 1] = acc[nt][1] * inv0;
        }
        if (s1) {
            o[ob1 + cc]     = acc[nt][2] * inv1;
            o[ob1 + cc + 1] = acc[nt][3] * inv1;
        }
    }
}

// ---------------- trilinear upsample of V + LN + add o -> fp16 hi/lo ----------------
__global__ void __launch_bounds__(256) ups_ln_add_kernel(
    const float* __restrict__ kv, const float* __restrict__ ob,
    const float* __restrict__ g, const float* __restrict__ beta,
    __half* __restrict__ yh, __half* __restrict__ yl)
{
    int bn = blockIdx.x;
    int b = bn / NTOK, n = bn % NTOK;
    int d = n / 400, hh = (n / 20) % 20, ww = n % 20;
    float sd = d  * 0.5f - 0.25f; int fd = (int)floorf(sd); float wdz = sd - (float)fd;
    float sh = hh * 0.5f - 0.25f; int fh = (int)floorf(sh); float why = sh - (float)fh;
    float sw = ww * 0.5f - 0.25f; int fw = (int)floorf(sw); float wwx = sw - (float)fw;
    int dz0 = fd < 0 ? 0 : fd; int dz1 = (fd + 1) > 9 ? 9 : (fd + 1);
    int hy0 = fh < 0 ? 0 : fh; int hy1 = (fh + 1) > 9 ? 9 : (fh + 1);
    int wx0 = fw < 0 ? 0 : fw; int wx1 = (fw + 1) > 9 ? 9 : (fw + 1);
    int midx[8]; float wt8[8];
    {
        int zz[2] = {dz0, dz1};  float wz[2] = {1.f - wdz, wdz};
        int yy[2] = {hy0, hy1};  float wy[2] = {1.f - why, why};
        int xx[2] = {wx0, wx1};  float wx[2] = {1.f - wwx, wwx};
        int t = 0;
        for (int a = 0; a < 2; a++)
            for (int b2 = 0; b2 < 2; b2++)
                for (int c2 = 0; c2 < 2; c2++) {
                    midx[t] = zz[a] * 100 + yy[b2] * 10 + xx[c2];
                    wt8[t]  = wz[a] * wy[b2] * wx[c2]; t++;
                }
    }
    __shared__ float vals[CDIM];
    __shared__ float red[18];
    size_t kvb = (size_t)b * NSR * 1024 + 512;
    float loc[2];
#pragma unroll
    for (int ci = 0; ci < 2; ci++) {
        int c = threadIdx.x + ci * 256;
        float acc = 0.f;
#pragma unroll
        for (int t = 0; t < 8; t++)
            acc += wt8[t] * kv[kvb + (size_t)midx[t] * 1024 + c];
        vals[c] = acc; loc[ci] = acc;
    }
    float s = loc[0] + loc[1], sq = loc[0] * loc[0] + loc[1] * loc[1];
#pragma unroll
    for (int o2 = 16; o2 > 0; o2 >>= 1) {
        s  += __shfl_down_sync(0xffffffffu, s,  o2);
        sq += __shfl_down_sync(0xffffffffu, sq, o2);
    }
    int w = threadIdx.x >> 5;
    if ((threadIdx.x & 31) == 0) { red[w] = s; red[8 + w] = sq; }
    __syncthreads();
    if (threadIdx.x == 0) {
        float a = 0.f, b2 = 0.f;
        for (int i = 0; i < 8; i++) { a += red[i]; b2 += red[8 + i]; }
        red[16] = a; red[17] = b2;
    }
    __syncthreads();
    float mean = red[16] * (1.f / CDIM);
    float var  = red[17] * (1.f / CDIM) - mean * mean;
    float inv  = rsqrtf(var + 1e-6f);
#pragma unroll
    for (int ci = 0; ci < 2; ci++) {
        int c = threadIdx.x + ci * 256;
        size_t oidx = ((size_t)b * NTOK + n) * CDIM + c;
        float v = ob[oidx] + (vals[c] - mean) * inv * g[c] + beta[c];
        __half hb = __float2half(v);
        yh[oidx] = hb;
        yl[oidx] = __float2half(v - __half2float(hb));
    }
}

// ---------------- launch ----------------
extern "C" void kernel_launch(void* const* d_in, const int* in_sizes, int n_in,
                              void* d_out, int out_size)
{
    const float* x      = (const float*)d_in[0];
    const float* Wq     = (const float*)d_in[1];
    const float* bq     = (const float*)d_in[2];
    const float* Wkv    = (const float*)d_in[3];
    const float* bkv    = (const float*)d_in[4];
    const float* srw    = (const float*)d_in[5];
    const float* srb    = (const float*)d_in[6];
    const float* srg    = (const float*)d_in[7];
    const float* srbeta = (const float*)d_in[8];
    const float* upg    = (const float*)d_in[9];
    const float* upbeta = (const float*)d_in[10];
    const float* Wp     = (const float*)d_in[11];
    const float* bp     = (const float*)d_in[12];
    float* out = (float*)d_out;

    float *kvb, *ob;
    __half *xh, *yh, *yl, *xrh, *xrl, *qh, *kvh, *wqt, *wkvt, *wpt;
    cudaGetSymbolAddress((void**)&kvb, g_kv);
    cudaGetSymbolAddress((void**)&ob,  g_o);
    cudaGetSymbolAddress((void**)&xh,  g_xh);
    cudaGetSymbolAddress((void**)&yh,  g_yh);
    cudaGetSymbolAddress((void**)&yl,  g_yl);
    cudaGetSymbolAddress((void**)&qh,  g_qh);
    cudaGetSymbolAddress((void**)&kvh, g_kvh);
    cudaGetSymbolAddress((void**)&xrh, g_xrh);
    cudaGetSymbolAddress((void**)&xrl, g_xrl);
    cudaGetSymbolAddress((void**)&wqt, g_wqt);
    cudaGetSymbolAddress((void**)&wkvt, g_wkvt);
    cudaGetSymbolAddress((void**)&wpt, g_wpt);

    int nx = BATCH * NTOK * CDIM;
    // attn_mma_kernel kept as the 6th launch for ncu -s 5 -c 1
    cvt_kernel<<<(nx + 255) / 256, 256>>>(x, xh, nx);                              // 1
    wsplit_all_kernel<<<1024, 256>>>(Wq, Wkv, Wp, wqt, wkvt, wpt);                 // 2
    conv_ln_kernel<<<BATCH * NSR, 256>>>(x, srw, srb, srg, srbeta, xrh, xrl);      // 3

    // kv = xr @ Wkv + bkv -> f32 (upsample) + fp16 (attention)
    gemm2h_kernel<<<dim3(1024 / 128, (BATCH * NSR + 127) / 128), 256>>>(           // 4
        xrh, xrl, wkvt, bkv, kvb, kvh, BATCH * NSR, 1024);
    // q = x @ Wq + bq -> fp16 (single-term: logit path, softmax-attenuated)
    gemm1h_kernel<<<dim3(512 / 128, (BATCH * NTOK) / 128), 256>>>(                 // 5
        xh, wqt, bq, qh, BATCH * NTOK, 512);

    attn_mma_kernel<<<dim3((NTOK + 127) / 128, BATCH * NHEADS), 256>>>(qh, kvh, ob); // 6

    ups_ln_add_kernel<<<BATCH * NTOK, 256>>>(kvb, ob, upg, upbeta, yh, yl);        // 7

    // out = (yh+yl) @ Wp + bp -> f32 (2-term fp16)
    gemm2h_kernel<<<dim3(512 / 128, (BATCH * NTOK) / 128), 256>>>(                 // 8
        yh, yl, wpt, bp, out, (__half*)nullptr, BATCH * NTOK, 512);
}

// round 13
// speedup vs baseline: 1.0712x; 1.0712x over previous
#include <cuda_runtime.h>
#include <cuda_bf16.h>
#include <cuda_fp16.h>
#include <math.h>
#include <float.h>
#include <stdint.h>

#define BATCH 2
#define NTOK  8000
#define CDIM  512
#define NSR   1000
#define NHEADS 8
#define HD    64

__device__ float g_kv[BATCH * NSR * 2 * CDIM];
__device__ float g_o [BATCH * NTOK * CDIM];
__device__ __half g_yh [BATCH * NTOK * CDIM];
__device__ __half g_yl [BATCH * NTOK * CDIM];
__device__ __half g_qh [BATCH * NTOK * CDIM];
__device__ __half g_kvh[BATCH * NSR * 2 * CDIM];
__device__ __half g_xrh[BATCH * NSR * CDIM];
__device__ __half g_xrl[BATCH * NSR * CDIM];
__device__ __half g_wqt [CDIM * CDIM];
__device__ __half g_wkvt[2 * CDIM * CDIM];
__device__ __half g_wpt [CDIM * CDIM];

// ---------------- ptx helpers ----------------
__device__ __forceinline__ void ldsm4(uint32_t& r0, uint32_t& r1, uint32_t& r2, uint32_t& r3,
                                      uint32_t addr)
{
    asm volatile("ldmatrix.sync.aligned.m8n8.x4.shared.b16 {%0,%1,%2,%3}, [%4];"
                 : "=r"(r0), "=r"(r1), "=r"(r2), "=r"(r3) : "r"(addr));
}
__device__ __forceinline__ void ldsm4t(uint32_t& r0, uint32_t& r1, uint32_t& r2, uint32_t& r3,
                                       uint32_t addr)
{
    asm volatile("ldmatrix.sync.aligned.m8n8.x4.trans.shared.b16 {%0,%1,%2,%3}, [%4];"
                 : "=r"(r0), "=r"(r1), "=r"(r2), "=r"(r3) : "r"(addr));
}
__device__ __forceinline__ void mma16816h(float* c, const uint32_t* a, const uint32_t* b)
{
    asm volatile("mma.sync.aligned.m16n8k16.row.col.f32.f16.f16.f32 "
                 "{%0,%1,%2,%3}, {%4,%5,%6,%7}, {%8,%9}, {%0,%1,%2,%3};"
                 : "+f"(c[0]), "+f"(c[1]), "+f"(c[2]), "+f"(c[3])
                 : "r"(a[0]), "r"(a[1]), "r"(a[2]), "r"(a[3]), "r"(b[0]), "r"(b[1]));
}
__device__ __forceinline__ uint32_t packh2(float a, float b) {
    __half2 t = __floats2half2_rn(a, b);
    return *(uint32_t*)&t;
}

// ---------------- transpose ALL weights to fp16 [N][K] in one launch ----------------
__global__ void __launch_bounds__(256) wsplit_all_kernel(
    const float* __restrict__ Wq, const float* __restrict__ Wkv,
    const float* __restrict__ Wp,
    __half* __restrict__ qt, __half* __restrict__ kt, __half* __restrict__ pt)
{
    __shared__ float t[32][33];
    int tb = blockIdx.x;
    const float* W; __half* T; int N, nb, kb;
    if (tb < 256)      { W = Wq;  T = qt; N = 512;  int tt = tb;       nb = (tt & 15) * 32; kb = (tt >> 4) * 32; }
    else if (tb < 768) { W = Wkv; T = kt; N = 1024; int tt = tb - 256; nb = (tt & 31) * 32; kb = (tt >> 5) * 32; }
    else               { W = Wp;  T = pt; N = 512;  int tt = tb - 768; nb = (tt & 15) * 32; kb = (tt >> 4) * 32; }
    const int K = 512;
    int tx = threadIdx.x & 31, ty = threadIdx.x >> 5;
#pragma unroll
    for (int i = ty; i < 32; i += 8)
        t[i][tx] = W[(size_t)(kb + i) * N + nb + tx];
    __syncthreads();
#pragma unroll
    for (int i = ty; i < 32; i += 8)
        T[(size_t)(nb + i) * K + kb + tx] = __float2half(t[tx][i]);
}

// ---------------- conv3d depthwise (3,s2,p1) + bias + LN -> fp16 hi/lo ----------------
__global__ void __launch_bounds__(256) conv_ln_kernel(
    const float* __restrict__ x, const float* __restrict__ srw,
    const float* __restrict__ srb, const float* __restrict__ g,
    const float* __restrict__ beta,
    __half* __restrict__ xrh, __half* __restrict__ xrl)
{
    int bp = blockIdx.x;
    int b = bp / NSR, opos = bp % NSR;
    int od = opos / 100, oh = (opos / 10) % 10, ow = opos % 10;
    __shared__ float vals[CDIM];
    __shared__ float red[18];
    float loc[2];
#pragma unroll
    for (int ci = 0; ci < 2; ci++) {
        int c = threadIdx.x + ci * 256;
        float acc = srb[c];
#pragma unroll
        for (int kd = 0; kd < 3; kd++) {
            int id = od * 2 - 1 + kd;
            if ((unsigned)id >= 20u) continue;
#pragma unroll
            for (int kh = 0; kh < 3; kh++) {
                int ih = oh * 2 - 1 + kh;
                if ((unsigned)ih >= 20u) continue;
#pragma unroll
                for (int kw = 0; kw < 3; kw++) {
                    int iw = ow * 2 - 1 + kw;
                    if ((unsigned)iw >= 20u) continue;
                    acc += x[((size_t)b * NTOK + id * 400 + ih * 20 + iw) * CDIM + c] *
                           srw[c * 27 + kd * 9 + kh * 3 + kw];
                }
            }
        }
        vals[c] = acc; loc[ci] = acc;
    }
    float s = loc[0] + loc[1], sq = loc[0] * loc[0] + loc[1] * loc[1];
#pragma unroll
    for (int o2 = 16; o2 > 0; o2 >>= 1) {
        s  += __shfl_down_sync(0xffffffffu, s,  o2);
        sq += __shfl_down_sync(0xffffffffu, sq, o2);
    }
    int w = threadIdx.x >> 5;
    if ((threadIdx.x & 31) == 0) { red[w] = s; red[8 + w] = sq; }
    __syncthreads();
    if (threadIdx.x == 0) {
        float a = 0.f, b2 = 0.f;
        for (int i = 0; i < 8; i++) { a += red[i]; b2 += red[8 + i]; }
        red[16] = a; red[17] = b2;
    }
    __syncthreads();
    float mean = red[16] * (1.f / CDIM);
    float var  = red[17] * (1.f / CDIM) - mean * mean;
    float inv  = rsqrtf(var + 1e-6f);
#pragma unroll
    for (int ci = 0; ci < 2; ci++) {
        int c = threadIdx.x + ci * 256;
        float v = (vals[c] - mean) * inv * g[c] + beta[c];
        size_t idx = ((size_t)b * NSR + opos) * CDIM + c;
        __half hh = __float2half(v);
        xrh[idx] = hh;
        xrl[idx] = __float2half(v - __half2float(hh));
    }
}

#define SMS 40

// ---------------- fp16 2-term GEMM: C = (Ah+Al)[M,512] @ B[N,512]^T + bias ----------------
__global__ void __launch_bounds__(256, 2) gemm2h_kernel(
    const __half* __restrict__ Ah, const __half* __restrict__ Al,
    const __half* __restrict__ B, const float* __restrict__ bias,
    float* __restrict__ C, __half* __restrict__ Ch, int M, int N)
{
    __shared__ __half sAh[128 * SMS], sAl[128 * SMS], sB[128 * SMS];

    int tid = threadIdx.x, wid = tid >> 5, lane = tid & 31;
    int wr = wid >> 2, wc = wid & 3;
    int rowBase = blockIdx.y * 128, colBase = blockIdx.x * 128;

    float acc[4][4][4];
#pragma unroll
    for (int i = 0; i < 4; i++)
#pragma unroll
        for (int j = 0; j < 4; j++)
#pragma unroll
            for (int k = 0; k < 4; k++) acc[i][j][k] = 0.f;

    uint32_t aBaseH = (uint32_t)__cvta_generic_to_shared(sAh);
    uint32_t aBaseL = (uint32_t)__cvta_generic_to_shared(sAl);
    uint32_t bBase  = (uint32_t)__cvta_generic_to_shared(sB);

    for (int k0 = 0; k0 < 512; k0 += 32) {
        __syncthreads();
#pragma unroll
        for (int it = 0; it < 2; it++) {
            int idx = tid + it * 256;
            int r = idx >> 2, c = idx & 3;
            int ar = rowBase + r; if (ar > M - 1) ar = M - 1;
            int br = colBase + r;
            size_t aoff = (size_t)ar * 512 + k0 + c * 8;
            size_t boff = (size_t)br * 512 + k0 + c * 8;
            int soff = r * SMS + c * 8;
            *(uint4*)&sAh[soff] = *(const uint4*)&Ah[aoff];
            *(uint4*)&sAl[soff] = *(const uint4*)&Al[aoff];
            *(uint4*)&sB [soff] = *(const uint4*)&B [boff];
        }
        __syncthreads();

#pragma unroll
        for (int ks = 0; ks < 32; ks += 16) {
            uint32_t aoffs = (uint32_t)(((wr * 64 + (lane & 15)) * SMS + ks + ((lane >> 4) << 3)) * 2);
            uint32_t boffs = (uint32_t)(((wc * 32 + ((lane >> 4) << 3) + (lane & 7)) * SMS + ks + (((lane >> 3) & 1) << 3)) * 2);

            uint32_t ah[4][4], al[4][4];
#pragma unroll
            for (int mf = 0; mf < 4; mf++) {
                uint32_t ao = aoffs + (uint32_t)(mf * 16 * SMS * 2);
                ldsm4(ah[mf][0], ah[mf][1], ah[mf][2], ah[mf][3], aBaseH + ao);
                ldsm4(al[mf][0], al[mf][1], al[mf][2], al[mf][3], aBaseL + ao);
            }
            uint32_t bh[4][2];
#pragma unroll
            for (int np = 0; np < 2; np++) {
                uint32_t bo = boffs + (uint32_t)(np * 16 * SMS * 2);
                ldsm4(bh[np * 2][0], bh[np * 2][1], bh[np * 2 + 1][0], bh[np * 2 + 1][1], bBase + bo);
            }
#pragma unroll
            for (int mf = 0; mf < 4; mf++)
#pragma unroll
                for (int nf = 0; nf < 4; nf++) {
                    mma16816h(acc[mf][nf], ah[mf], bh[nf]);
                    mma16816h(acc[mf][nf], al[mf], bh[nf]);
                }
        }
    }

#pragma unroll
    for (int mf = 0; mf < 4; mf++) {
#pragma unroll
        for (int nf = 0; nf < 4; nf++) {
            int row0 = rowBase + wr * 64 + mf * 16 + (lane >> 2);
            int col  = colBase + wc * 32 + nf * 8 + 2 * (lane & 3);
            float b0 = bias[col], b1 = bias[col + 1];
#pragma unroll
            for (int half = 0; half < 2; half++) {
                int row = row0 + half * 8;
                if (row < M) {
                    float v0 = acc[mf][nf][half * 2]     + b0;
                    float v1 = acc[mf][nf][half * 2 + 1] + b1;
                    size_t o0 = (size_t)row * N + col;
                    if (C) { C[o0] = v0; C[o0 + 1] = v1; }
                    if (Ch) {
                        Ch[o0]     = __float2half(v0);
                        Ch[o0 + 1] = __float2half(v1);
                    }
                }
            }
        }
    }
}

// ---------------- fp16 1-term GEMM with fused f32->fp16 A conversion ----------------
// C = cvt16(A_f32)[M,512] @ B[N,512]^T + bias -> fp16
__global__ void __launch_bounds__(256, 2) gemm1hf_kernel(
    const float* __restrict__ A, const __half* __restrict__ B,
    const float* __restrict__ bias, __half* __restrict__ Ch, int M, int N)
{
    __shared__ __half sA[128 * SMS], sB[128 * SMS];

    int tid = threadIdx.x, wid = tid >> 5, lane = tid & 31;
    int wr = wid >> 2, wc = wid & 3;
    int rowBase = blockIdx.y * 128, colBase = blockIdx.x * 128;

    float acc[4][4][4];
#pragma unroll
    for (int i = 0; i < 4; i++)
#pragma unroll
        for (int j = 0; j < 4; j++)
#pragma unroll
            for (int k = 0; k < 4; k++) acc[i][j][k] = 0.f;

    uint32_t aBase = (uint32_t)__cvta_generic_to_shared(sA);
    uint32_t bBase = (uint32_t)__cvta_generic_to_shared(sB);

    for (int k0 = 0; k0 < 512; k0 += 32) {
        __syncthreads();
#pragma unroll
        for (int it = 0; it < 2; it++) {
            int idx = tid + it * 256;
            int r = idx >> 2, c = idx & 3;
            int ar = rowBase + r; if (ar > M - 1) ar = M - 1;
            int br = colBase + r;
            size_t aoff = (size_t)ar * 512 + k0 + c * 8;
            size_t boff = (size_t)br * 512 + k0 + c * 8;
            int soff = r * SMS + c * 8;
            float4 f0 = *(const float4*)&A[aoff];
            float4 f1 = *(const float4*)&A[aoff + 4];
            __half2 h0 = __floats2half2_rn(f0.x, f0.y);
            __half2 h1 = __floats2half2_rn(f0.z, f0.w);
            __half2 h2 = __floats2half2_rn(f1.x, f1.y);
            __half2 h3 = __floats2half2_rn(f1.z, f1.w);
            uint4 pk;
            pk.x = *(uint32_t*)&h0; pk.y = *(uint32_t*)&h1;
            pk.z = *(uint32_t*)&h2; pk.w = *(uint32_t*)&h3;
            *(uint4*)&sA[soff] = pk;
            *(uint4*)&sB[soff] = *(const uint4*)&B[boff];
        }
        __syncthreads();

#pragma unroll
        for (int ks = 0; ks < 32; ks += 16) {
            uint32_t aoffs = (uint32_t)(((wr * 64 + (lane & 15)) * SMS + ks + ((lane >> 4) << 3)) * 2);
            uint32_t boffs = (uint32_t)(((wc * 32 + ((lane >> 4) << 3) + (lane & 7)) * SMS + ks + (((lane >> 3) & 1) << 3)) * 2);

            uint32_t a_[4][4];
#pragma unroll
            for (int mf = 0; mf < 4; mf++) {
                uint32_t ao = aoffs + (uint32_t)(mf * 16 * SMS * 2);
                ldsm4(a_[mf][0], a_[mf][1], a_[mf][2], a_[mf][3], aBase + ao);
            }
            uint32_t bh[4][2];
#pragma unroll
            for (int np = 0; np < 2; np++) {
                uint32_t bo = boffs + (uint32_t)(np * 16 * SMS * 2);
                ldsm4(bh[np * 2][0], bh[np * 2][1], bh[np * 2 + 1][0], bh[np * 2 + 1][1], bBase + bo);
            }
#pragma unroll
            for (int mf = 0; mf < 4; mf++)
#pragma unroll
                for (int nf = 0; nf < 4; nf++)
                    mma16816h(acc[mf][nf], a_[mf], bh[nf]);
        }
    }

#pragma unroll
    for (int mf = 0; mf < 4; mf++) {
#pragma unroll
        for (int nf = 0; nf < 4; nf++) {
            int row0 = rowBase + wr * 64 + mf * 16 + (lane >> 2);
            int col  = colBase + wc * 32 + nf * 8 + 2 * (lane & 3);
            float b0 = bias[col], b1 = bias[col + 1];
#pragma unroll
            for (int half = 0; half < 2; half++) {
                int row = row0 + half * 8;
                if (row < M) {
                    size_t o0 = (size_t)row * N + col;
                    Ch[o0]     = __float2half(acc[mf][nf][half * 2]     + b0);
                    Ch[o0 + 1] = __float2half(acc[mf][nf][half * 2 + 1] + b1);
                }
            }
        }
    }
}

// ---------------- flash attention: 64-query tile, 128 thr, all-fp16, base-2 softmax ----------------
#define AST 72
#define AT_SCALE 0.18033688f   // 0.125 * log2(e)
__global__ void __launch_bounds__(128) attn_mma_kernel(
    const __half* __restrict__ q, const __half* __restrict__ kvh,
    float* __restrict__ o)
{
    __shared__ __half sQ[64 * AST];
    __shared__ __half sK[64 * AST];
    __shared__ __half sV[64 * AST];

    int tid = threadIdx.x, wid = tid >> 5, lane = tid & 31;
    int bh = blockIdx.y, b = bh >> 3, h = bh & 7;
    int qbase = blockIdx.x * 64;
    size_t qoff = ((size_t)b * NTOK + qbase) * CDIM + h * HD;

#pragma unroll
    for (int i = 0; i < 4; i++) {
        int idx = tid + i * 128;
        int r = idx >> 3, c = (idx & 7) << 3;
        *(uint4*)&sQ[r * AST + c] = *(const uint4*)&q[qoff + (size_t)r * CDIM + c];
    }
    __syncthreads();

    uint32_t bQ = (uint32_t)__cvta_generic_to_shared(sQ);
    uint32_t bK = (uint32_t)__cvta_generic_to_shared(sK);
    uint32_t bV = (uint32_t)__cvta_generic_to_shared(sV);

    uint32_t qf[4][4];
    {
        uint32_t qrow = (uint32_t)(wid * 16 + (lane & 15));
#pragma unroll
        for (int kt = 0; kt < 4; kt++) {
            uint32_t off = (qrow * AST + kt * 16 + ((lane >> 4) << 3)) * 2;
            ldsm4(qf[kt][0], qf[kt][1], qf[kt][2], qf[kt][3], bQ + off);
        }
    }

    float acc[8][4];
#pragma unroll
    for (int i = 0; i < 8; i++)
#pragma unroll
        for (int j = 0; j < 4; j++) acc[i][j] = 0.f;
    float m0 = -FLT_MAX, m1 = -FLT_MAX, l0 = 0.f, l1 = 0.f;

    size_t kvoff = (size_t)b * NSR * 1024 + h * HD;
    int cbase = 2 * (lane & 3);

    for (int kb = 0; kb < NSR; kb += 64) {
        __syncthreads();
#pragma unroll
        for (int i = 0; i < 4; i++) {
            int idx = tid + i * 128;
            int r = idx >> 3, c = (idx & 7) << 3;
            int gm = kb + r;
            uint4 z = make_uint4(0u, 0u, 0u, 0u);
            uint4 a0 = z, a1 = z;
            if (gm < NSR) {
                size_t base = kvoff + (size_t)gm * 1024 + c;
                a0 = *(const uint4*)&kvh[base];
                a1 = *(const uint4*)&kvh[base + 512];
            }
            *(uint4*)&sK[r * AST + c] = a0;
            *(uint4*)&sV[r * AST + c] = a1;
        }
        __syncthreads();

        float s_[8][4];
#pragma unroll
        for (int i = 0; i < 8; i++)
#pragma unroll
            for (int j = 0; j < 4; j++) s_[i][j] = 0.f;

#pragma unroll
        for (int kt = 0; kt < 4; kt++) {
#pragma unroll
            for (int np = 0; np < 4; np++) {
                uint32_t brow = (uint32_t)(np * 16 + ((lane >> 4) << 3) + (lane & 7));
                uint32_t boff = (brow * AST + kt * 16 + (((lane >> 3) & 1) << 3)) * 2;
                uint32_t h0, h1, h2, h3;
                ldsm4(h0, h1, h2, h3, bK + boff);
                uint32_t fh0[2] = {h0, h1}, fh1[2] = {h2, h3};
                mma16816h(s_[np * 2],     qf[kt], fh0);
                mma16816h(s_[np * 2 + 1], qf[kt], fh1);
            }
        }

        int valid = NSR - kb; if (valid > 64) valid = 64;
        float rm0 = -FLT_MAX, rm1 = -FLT_MAX;
#pragma unroll
        for (int nt = 0; nt < 8; nt++) {
#pragma unroll
            for (int j = 0; j < 4; j++) s_[nt][j] *= AT_SCALE;
            rm0 = fmaxf(rm0, fmaxf(s_[nt][0], s_[nt][1]));
            rm1 = fmaxf(rm1, fmaxf(s_[nt][2], s_[nt][3]));
        }
        rm0 = fmaxf(rm0, __shfl_xor_sync(0xffffffffu, rm0, 1));
        rm0 = fmaxf(rm0, __shfl_xor_sync(0xffffffffu, rm0, 2));
        rm1 = fmaxf(rm1, __shfl_xor_sync(0xffffffffu, rm1, 1));
        rm1 = fmaxf(rm1, __shfl_xor_sync(0xffffffffu, rm1, 2));
        float nm0 = fmaxf(m0, rm0), nm1 = fmaxf(m1, rm1);
        float corr0 = exp2f(m0 - nm0), corr1 = exp2f(m1 - nm1);
        m0 = nm0; m1 = nm1;

        float sum0 = 0.f, sum1 = 0.f;
#pragma unroll
        for (int nt = 0; nt < 8; nt++) {
            int c0 = nt * 8 + cbase;
            float p0 = (c0     < valid) ? exp2f(s_[nt][0] - nm0) : 0.f;
            float p1 = (c0 + 1 < valid) ? exp2f(s_[nt][1] - nm0) : 0.f;
            float p2 = (c0     < valid) ? exp2f(s_[nt][2] - nm1) : 0.f;
            float p3 = (c0 + 1 < valid) ? exp2f(s_[nt][3] - nm1) : 0.f;
            sum0 += p0 + p1; sum1 += p2 + p3;
            s_[nt][0] = p0; s_[nt][1] = p1; s_[nt][2] = p2; s_[nt][3] = p3;
        }
        sum0 += __shfl_xor_sync(0xffffffffu, sum0, 1);
        sum0 += __shfl_xor_sync(0xffffffffu, sum0, 2);
        sum1 += __shfl_xor_sync(0xffffffffu, sum1, 1);
        sum1 += __shfl_xor_sync(0xffffffffu, sum1, 2);
        l0 = l0 * corr0 + sum0;
        l1 = l1 * corr1 + sum1;

#pragma unroll
        for (int nt = 0; nt < 8; nt++) {
            acc[nt][0] *= corr0; acc[nt][1] *= corr0;
            acc[nt][2] *= corr1; acc[nt][3] *= corr1;
        }

#pragma unroll
        for (int kt = 0; kt < 4; kt++) {
            uint32_t ph[4];
#pragma unroll
            for (int q2 = 0; q2 < 2; q2++) {
                int nt = 2 * kt + q2;
                ph[q2 * 2]     = packh2(s_[nt][0], s_[nt][1]);
                ph[q2 * 2 + 1] = packh2(s_[nt][2], s_[nt][3]);
            }
            int l8 = lane >> 3, li = lane & 7;
#pragma unroll
            for (int np = 0; np < 4; np++) {
                uint32_t vrow = (uint32_t)(kt * 16 + ((l8 & 1) << 3) + li);
                uint32_t vcol = (uint32_t)(np * 16 + ((l8 >> 1) << 3));
                uint32_t voff = (vrow * AST + vcol) * 2;
                uint32_t h0, h1, h2, h3;
                ldsm4t(h0, h1, h2, h3, bV + voff);
                uint32_t fh0[2] = {h0, h1}, fh1[2] = {h2, h3};
                mma16816h(acc[np * 2],     ph, fh0);
                mma16816h(acc[np * 2 + 1], ph, fh1);
            }
        }
    }

    float inv0 = 1.f / l0, inv1 = 1.f / l1;
    int r0 = qbase + wid * 16 + (lane >> 2);
    size_t ob0 = ((size_t)b * NTOK + r0) * CDIM + h * HD;
    size_t ob1 = ob0 + (size_t)8 * CDIM;
#pragma unroll
    for (int nt = 0; nt < 8; nt++) {
        int cc = nt * 8 + cbase;
        o[ob0 + cc]     = acc[nt][0] * inv0;
        o[ob0 + cc + 1] = acc[nt][1] * inv0;
        o[ob1 + cc]     = acc[nt][2] * inv1;
        o[ob1 + cc + 1] = acc[nt][3] * inv1;
    }
}

// ---------------- trilinear upsample of V + LN + add o -> fp16 hi/lo ----------------
__global__ void __launch_bounds__(256) ups_ln_add_kernel(
    const float* __restrict__ kv, const float* __restrict__ ob,
    const float* __restrict__ g, const float* __restrict__ beta,
    __half* __restrict__ yh, __half* __restrict__ yl)
{
    int bn = blockIdx.x;
    int b = bn / NTOK, n = bn % NTOK;
    int d = n / 400, hh = (n / 20) % 20, ww = n % 20;
    float sd = d  * 0.5f - 0.25f; int fd = (int)floorf(sd); float wdz = sd - (float)fd;
    float sh = hh * 0.5f - 0.25f; int fh = (int)floorf(sh); float why = sh - (float)fh;
    float sw = ww * 0.5f - 0.25f; int fw = (int)floorf(sw); float wwx = sw - (float)fw;
    int dz0 = fd < 0 ? 0 : fd; int dz1 = (fd + 1) > 9 ? 9 : (fd + 1);
    int hy0 = fh < 0 ? 0 : fh; int hy1 = (fh + 1) > 9 ? 9 : (fh + 1);
    int wx0 = fw < 0 ? 0 : fw; int wx1 = (fw + 1) > 9 ? 9 : (fw + 1);
    int midx[8]; float wt8[8];
    {
        int zz[2] = {dz0, dz1};  float wz[2] = {1.f - wdz, wdz};
        int yy[2] = {hy0, hy1};  float wy[2] = {1.f - why, why};
        int xx[2] = {wx0, wx1};  float wx[2] = {1.f - wwx, wwx};
        int t = 0;
        for (int a = 0; a < 2; a++)
            for (int b2 = 0; b2 < 2; b2++)
                for (int c2 = 0; c2 < 2; c2++) {
                    midx[t] = zz[a] * 100 + yy[b2] * 10 + xx[c2];
                    wt8[t]  = wz[a] * wy[b2] * wx[c2]; t++;
                }
    }
    __shared__ float vals[CDIM];
    __shared__ float red[18];
    size_t kvb = (size_t)b * NSR * 1024 + 512;
    float loc[2];
#pragma unroll
    for (int ci = 0; ci < 2; ci++) {
        int c = threadIdx.x + ci * 256;
        float acc = 0.f;
#pragma unroll
        for (int t = 0; t < 8; t++)
            acc += wt8[t] * kv[kvb + (size_t)midx[t] * 1024 + c];
        vals[c] = acc; loc[ci] = acc;
    }
    float s = loc[0] + loc[1], sq = loc[0] * loc[0] + loc[1] * loc[1];
#pragma unroll
    for (int o2 = 16; o2 > 0; o2 >>= 1) {
        s  += __shfl_down_sync(0xffffffffu, s,  o2);
        sq += __shfl_down_sync(0xffffffffu, sq, o2);
    }
    int w = threadIdx.x >> 5;
    if ((threadIdx.x & 31) == 0) { red[w] = s; red[8 + w] = sq; }
    __syncthreads();
    if (threadIdx.x == 0) {
        float a = 0.f, b2 = 0.f;
        for (int i = 0; i < 8; i++) { a += red[i]; b2 += red[8 + i]; }
        red[16] = a; red[17] = b2;
    }
    __syncthreads();
    float mean = red[16] * (1.f / CDIM);
    float var  = red[17] * (1.f / CDIM) - mean * mean;
    float inv  = rsqrtf(var + 1e-6f);
#pragma unroll
    for (int ci = 0; ci < 2; ci++) {
        int c = threadIdx.x + ci * 256;
        size_t oidx = ((size_t)b * NTOK + n) * CDIM + c;
        float v = ob[oidx] + (vals[c] - mean) * inv * g[c] + beta[c];
        __half hb = __float2half(v);
        yh[oidx] = hb;
        yl[oidx] = __float2half(v - __half2float(hb));
    }
}

// ---------------- launch ----------------
extern "C" void kernel_launch(void* const* d_in, const int* in_sizes, int n_in,
                              void* d_out, int out_size)
{
    const float* x      = (const float*)d_in[0];
    const float* Wq     = (const float*)d_in[1];
    const float* bq     = (const float*)d_in[2];
    const float* Wkv    = (const float*)d_in[3];
    const float* bkv    = (const float*)d_in[4];
    const float* srw    = (const float*)d_in[5];
    const float* srb    = (const float*)d_in[6];
    const float* srg    = (const float*)d_in[7];
    const float* srbeta = (const float*)d_in[8];
    const float* upg    = (const float*)d_in[9];
    const float* upbeta = (const float*)d_in[10];
    const float* Wp     = (const float*)d_in[11];
    const float* bp     = (const float*)d_in[12];
    float* out = (float*)d_out;

    float *kvb, *ob;
    __half *yh, *yl, *xrh, *xrl, *qh, *kvh, *wqt, *wkvt, *wpt;
    cudaGetSymbolAddress((void**)&kvb, g_kv);
    cudaGetSymbolAddress((void**)&ob,  g_o);
    cudaGetSymbolAddress((void**)&yh,  g_yh);
    cudaGetSymbolAddress((void**)&yl,  g_yl);
    cudaGetSymbolAddress((void**)&qh,  g_qh);
    cudaGetSymbolAddress((void**)&kvh, g_kvh);
    cudaGetSymbolAddress((void**)&xrh, g_xrh);
    cudaGetSymbolAddress((void**)&xrl, g_xrl);
    cudaGetSymbolAddress((void**)&wqt, g_wqt);
    cudaGetSymbolAddress((void**)&wkvt, g_wkvt);
    cudaGetSymbolAddress((void**)&wpt, g_wpt);

    // launch order keeps attn as 5th; ncu -s 5 -c 1 lands on attn or ups (both useful)
    wsplit_all_kernel<<<1024, 256>>>(Wq, Wkv, Wp, wqt, wkvt, wpt);                 // 1
    conv_ln_kernel<<<BATCH * NSR, 256>>>(x, srw, srb, srg, srbeta, xrh, xrl);      // 2

    // kv = xr @ Wkv + bkv -> f32 (upsample) + fp16 (attention)
    gemm2h_kernel<<<dim3(1024 / 128, (BATCH * NSR + 127) / 128), 256>>>(           // 3
        xrh, xrl, wkvt, bkv, kvb, kvh, BATCH * NSR, 1024);
    // q = cvt16(x) @ Wq + bq -> fp16 (fused conversion)
    gemm1hf_kernel<<<dim3(512 / 128, (BATCH * NTOK) / 128), 256>>>(                // 4
        x, wqt, bq, qh, BATCH * NTOK, 512);

    attn_mma_kernel<<<dim3(NTOK / 64, BATCH * NHEADS), 128>>>(qh, kvh, ob);        // 5

    ups_ln_add_kernel<<<BATCH * NTOK, 256>>>(kvb, ob, upg, upbeta, yh, yl);        // 6

    // out = (yh+yl) @ Wp + bp -> f32 (2-term fp16)
    gemm2h_kernel<<<dim3(512 / 128, (BATCH * NTOK) / 128), 256>>>(                 // 7
        yh, yl, wpt, bp, out, (__half*)nullptr, BATCH * NTOK, 512);
}

// round 14
// speedup vs baseline: 1.1114x; 1.0375x over previous
#include <cuda_runtime.h>
#include <cuda_bf16.h>
#include <cuda_fp16.h>
#include <math.h>
#include <float.h>
#include <stdint.h>

#define BATCH 2
#define NTOK  8000
#define CDIM  512
#define NSR   1000
#define NHEADS 8
#define HD    64

__device__ float g_kv[BATCH * NSR * 2 * CDIM];
__device__ float g_o [BATCH * NTOK * CDIM];
__device__ __half g_yh [BATCH * NTOK * CDIM];
__device__ __half g_yl [BATCH * NTOK * CDIM];
__device__ __half g_qh [BATCH * NTOK * CDIM];
__device__ __half g_kvh[BATCH * NSR * 2 * CDIM];
__device__ __half g_xrh[BATCH * NSR * CDIM];
__device__ __half g_xrl[BATCH * NSR * CDIM];
__device__ __half g_wqt [CDIM * CDIM];
__device__ __half g_wkvt[2 * CDIM * CDIM];
__device__ __half g_wpt [CDIM * CDIM];

// ---------------- ptx helpers ----------------
__device__ __forceinline__ void ldsm4(uint32_t& r0, uint32_t& r1, uint32_t& r2, uint32_t& r3,
                                      uint32_t addr)
{
    asm volatile("ldmatrix.sync.aligned.m8n8.x4.shared.b16 {%0,%1,%2,%3}, [%4];"
                 : "=r"(r0), "=r"(r1), "=r"(r2), "=r"(r3) : "r"(addr));
}
__device__ __forceinline__ void ldsm4t(uint32_t& r0, uint32_t& r1, uint32_t& r2, uint32_t& r3,
                                       uint32_t addr)
{
    asm volatile("ldmatrix.sync.aligned.m8n8.x4.trans.shared.b16 {%0,%1,%2,%3}, [%4];"
                 : "=r"(r0), "=r"(r1), "=r"(r2), "=r"(r3) : "r"(addr));
}
__device__ __forceinline__ void mma16816h(float* c, const uint32_t* a, const uint32_t* b)
{
    asm volatile("mma.sync.aligned.m16n8k16.row.col.f32.f16.f16.f32 "
                 "{%0,%1,%2,%3}, {%4,%5,%6,%7}, {%8,%9}, {%0,%1,%2,%3};"
                 : "+f"(c[0]), "+f"(c[1]), "+f"(c[2]), "+f"(c[3])
                 : "r"(a[0]), "r"(a[1]), "r"(a[2]), "r"(a[3]), "r"(b[0]), "r"(b[1]));
}
__device__ __forceinline__ uint32_t packh2(float a, float b) {
    __half2 t = __floats2half2_rn(a, b);
    return *(uint32_t*)&t;
}

// ---------------- transpose ALL weights to fp16 [N][K] in one launch ----------------
__global__ void __launch_bounds__(256) wsplit_all_kernel(
    const float* __restrict__ Wq, const float* __restrict__ Wkv,
    const float* __restrict__ Wp,
    __half* __restrict__ qt, __half* __restrict__ kt, __half* __restrict__ pt)
{
    __shared__ float t[32][33];
    int tb = blockIdx.x;
    const float* W; __half* T; int N, nb, kb;
    if (tb < 256)      { W = Wq;  T = qt; N = 512;  int tt = tb;       nb = (tt & 15) * 32; kb = (tt >> 4) * 32; }
    else if (tb < 768) { W = Wkv; T = kt; N = 1024; int tt = tb - 256; nb = (tt & 31) * 32; kb = (tt >> 5) * 32; }
    else               { W = Wp;  T = pt; N = 512;  int tt = tb - 768; nb = (tt & 15) * 32; kb = (tt >> 4) * 32; }
    const int K = 512;
    int tx = threadIdx.x & 31, ty = threadIdx.x >> 5;
#pragma unroll
    for (int i = ty; i < 32; i += 8)
        t[i][tx] = W[(size_t)(kb + i) * N + nb + tx];
    __syncthreads();
#pragma unroll
    for (int i = ty; i < 32; i += 8)
        T[(size_t)(nb + i) * K + kb + tx] = __float2half(t[tx][i]);
}

// ---------------- conv3d depthwise (3,s2,p1) + bias + LN -> fp16 hi/lo ----------------
__global__ void __launch_bounds__(256) conv_ln_kernel(
    const float* __restrict__ x, const float* __restrict__ srw,
    const float* __restrict__ srb, const float* __restrict__ g,
    const float* __restrict__ beta,
    __half* __restrict__ xrh, __half* __restrict__ xrl)
{
    int bp = blockIdx.x;
    int b = bp / NSR, opos = bp % NSR;
    int od = opos / 100, oh = (opos / 10) % 10, ow = opos % 10;
    __shared__ float vals[CDIM];
    __shared__ float red[18];
    float loc[2];
#pragma unroll
    for (int ci = 0; ci < 2; ci++) {
        int c = threadIdx.x + ci * 256;
        float acc = srb[c];
#pragma unroll
        for (int kd = 0; kd < 3; kd++) {
            int id = od * 2 - 1 + kd;
            if ((unsigned)id >= 20u) continue;
#pragma unroll
            for (int kh = 0; kh < 3; kh++) {
                int ih = oh * 2 - 1 + kh;
                if ((unsigned)ih >= 20u) continue;
#pragma unroll
                for (int kw = 0; kw < 3; kw++) {
                    int iw = ow * 2 - 1 + kw;
                    if ((unsigned)iw >= 20u) continue;
                    acc += x[((size_t)b * NTOK + id * 400 + ih * 20 + iw) * CDIM + c] *
                           srw[c * 27 + kd * 9 + kh * 3 + kw];
                }
            }
        }
        vals[c] = acc; loc[ci] = acc;
    }
    float s = loc[0] + loc[1], sq = loc[0] * loc[0] + loc[1] * loc[1];
#pragma unroll
    for (int o2 = 16; o2 > 0; o2 >>= 1) {
        s  += __shfl_down_sync(0xffffffffu, s,  o2);
        sq += __shfl_down_sync(0xffffffffu, sq, o2);
    }
    int w = threadIdx.x >> 5;
    if ((threadIdx.x & 31) == 0) { red[w] = s; red[8 + w] = sq; }
    __syncthreads();
    if (threadIdx.x == 0) {
        float a = 0.f, b2 = 0.f;
        for (int i = 0; i < 8; i++) { a += red[i]; b2 += red[8 + i]; }
        red[16] = a; red[17] = b2;
    }
    __syncthreads();
    float mean = red[16] * (1.f / CDIM);
    float var  = red[17] * (1.f / CDIM) - mean * mean;
    float inv  = rsqrtf(var + 1e-6f);
#pragma unroll
    for (int ci = 0; ci < 2; ci++) {
        int c = threadIdx.x + ci * 256;
        float v = (vals[c] - mean) * inv * g[c] + beta[c];
        size_t idx = ((size_t)b * NSR + opos) * CDIM + c;
        __half hh = __float2half(v);
        xrh[idx] = hh;
        xrl[idx] = __float2half(v - __half2float(hh));
    }
}

#define SMS 72   // row stride for BK=64 tiles (144B: ldmatrix conflict-free)

// ---------------- fp16 2-term GEMM (BK=64): C = (Ah+Al)[M,512] @ B[N,512]^T + bias ----------------
__global__ void __launch_bounds__(256, 2) gemm2h_kernel(
    const __half* __restrict__ Ah, const __half* __restrict__ Al,
    const __half* __restrict__ B, const float* __restrict__ bias,
    float* __restrict__ C, __half* __restrict__ Ch, int M, int N)
{
    __shared__ __half sAh[128 * SMS], sAl[128 * SMS], sB[128 * SMS];

    int tid = threadIdx.x, wid = tid >> 5, lane = tid & 31;
    int wr = wid >> 2, wc = wid & 3;
    int rowBase = blockIdx.y * 128, colBase = blockIdx.x * 128;

    float acc[4][4][4];
#pragma unroll
    for (int i = 0; i < 4; i++)
#pragma unroll
        for (int j = 0; j < 4; j++)
#pragma unroll
            for (int k = 0; k < 4; k++) acc[i][j][k] = 0.f;

    uint32_t aBaseH = (uint32_t)__cvta_generic_to_shared(sAh);
    uint32_t aBaseL = (uint32_t)__cvta_generic_to_shared(sAl);
    uint32_t bBase  = (uint32_t)__cvta_generic_to_shared(sB);

    for (int k0 = 0; k0 < 512; k0 += 64) {
        __syncthreads();
#pragma unroll
        for (int it = 0; it < 4; it++) {
            int idx = tid + it * 256;          // 0..1023
            int r = idx >> 3, c = idx & 7;     // 8 x 16B segments per 64-wide row
            int ar = rowBase + r; if (ar > M - 1) ar = M - 1;
            int br = colBase + r;
            size_t aoff = (size_t)ar * 512 + k0 + c * 8;
            size_t boff = (size_t)br * 512 + k0 + c * 8;
            int soff = r * SMS + c * 8;
            *(uint4*)&sAh[soff] = *(const uint4*)&Ah[aoff];
            *(uint4*)&sAl[soff] = *(const uint4*)&Al[aoff];
            *(uint4*)&sB [soff] = *(const uint4*)&B [boff];
        }
        __syncthreads();

#pragma unroll
        for (int ks = 0; ks < 64; ks += 16) {
            uint32_t aoffs = (uint32_t)(((wr * 64 + (lane & 15)) * SMS + ks + ((lane >> 4) << 3)) * 2);
            uint32_t boffs = (uint32_t)(((wc * 32 + ((lane >> 4) << 3) + (lane & 7)) * SMS + ks + (((lane >> 3) & 1) << 3)) * 2);

            uint32_t ah[4][4], al[4][4];
#pragma unroll
            for (int mf = 0; mf < 4; mf++) {
                uint32_t ao = aoffs + (uint32_t)(mf * 16 * SMS * 2);
                ldsm4(ah[mf][0], ah[mf][1], ah[mf][2], ah[mf][3], aBaseH + ao);
                ldsm4(al[mf][0], al[mf][1], al[mf][2], al[mf][3], aBaseL + ao);
            }
            uint32_t bh[4][2];
#pragma unroll
            for (int np = 0; np < 2; np++) {
                uint32_t bo = boffs + (uint32_t)(np * 16 * SMS * 2);
                ldsm4(bh[np * 2][0], bh[np * 2][1], bh[np * 2 + 1][0], bh[np * 2 + 1][1], bBase + bo);
            }
#pragma unroll
            for (int mf = 0; mf < 4; mf++)
#pragma unroll
                for (int nf = 0; nf < 4; nf++) {
                    mma16816h(acc[mf][nf], ah[mf], bh[nf]);
                    mma16816h(acc[mf][nf], al[mf], bh[nf]);
                }
        }
    }

#pragma unroll
    for (int mf = 0; mf < 4; mf++) {
#pragma unroll
        for (int nf = 0; nf < 4; nf++) {
            int row0 = rowBase + wr * 64 + mf * 16 + (lane >> 2);
            int col  = colBase + wc * 32 + nf * 8 + 2 * (lane & 3);
            float b0 = bias[col], b1 = bias[col + 1];
#pragma unroll
            for (int half = 0; half < 2; half++) {
                int row = row0 + half * 8;
                if (row < M) {
                    float v0 = acc[mf][nf][half * 2]     + b0;
                    float v1 = acc[mf][nf][half * 2 + 1] + b1;
                    size_t o0 = (size_t)row * N + col;
                    if (C) { C[o0] = v0; C[o0 + 1] = v1; }
                    if (Ch) {
                        Ch[o0]     = __float2half(v0);
                        Ch[o0 + 1] = __float2half(v1);
                    }
                }
            }
        }
    }
}

// ---------------- fp16 1-term GEMM (BK=64) with fused f32->fp16 A conversion ----------------
__global__ void __launch_bounds__(256, 2) gemm1hf_kernel(
    const float* __restrict__ A, const __half* __restrict__ B,
    const float* __restrict__ bias, __half* __restrict__ Ch, int M, int N)
{
    __shared__ __half sA[128 * SMS], sB[128 * SMS];

    int tid = threadIdx.x, wid = tid >> 5, lane = tid & 31;
    int wr = wid >> 2, wc = wid & 3;
    int rowBase = blockIdx.y * 128, colBase = blockIdx.x * 128;

    float acc[4][4][4];
#pragma unroll
    for (int i = 0; i < 4; i++)
#pragma unroll
        for (int j = 0; j < 4; j++)
#pragma unroll
            for (int k = 0; k < 4; k++) acc[i][j][k] = 0.f;

    uint32_t aBase = (uint32_t)__cvta_generic_to_shared(sA);
    uint32_t bBase = (uint32_t)__cvta_generic_to_shared(sB);

    for (int k0 = 0; k0 < 512; k0 += 64) {
        __syncthreads();
#pragma unroll
        for (int it = 0; it < 4; it++) {
            int idx = tid + it * 256;
            int r = idx >> 3, c = idx & 7;
            int ar = rowBase + r; if (ar > M - 1) ar = M - 1;
            int br = colBase + r;
            size_t aoff = (size_t)ar * 512 + k0 + c * 8;
            size_t boff = (size_t)br * 512 + k0 + c * 8;
            int soff = r * SMS + c * 8;
            float4 f0 = *(const float4*)&A[aoff];
            float4 f1 = *(const float4*)&A[aoff + 4];
            __half2 h0 = __floats2half2_rn(f0.x, f0.y);
            __half2 h1 = __floats2half2_rn(f0.z, f0.w);
            __half2 h2 = __floats2half2_rn(f1.x, f1.y);
            __half2 h3 = __floats2half2_rn(f1.z, f1.w);
            uint4 pk;
            pk.x = *(uint32_t*)&h0; pk.y = *(uint32_t*)&h1;
            pk.z = *(uint32_t*)&h2; pk.w = *(uint32_t*)&h3;
            *(uint4*)&sA[soff] = pk;
            *(uint4*)&sB[soff] = *(const uint4*)&B[boff];
        }
        __syncthreads();

#pragma unroll
        for (int ks = 0; ks < 64; ks += 16) {
            uint32_t aoffs = (uint32_t)(((wr * 64 + (lane & 15)) * SMS + ks + ((lane >> 4) << 3)) * 2);
            uint32_t boffs = (uint32_t)(((wc * 32 + ((lane >> 4) << 3) + (lane & 7)) * SMS + ks + (((lane >> 3) & 1) << 3)) * 2);

            uint32_t a_[4][4];
#pragma unroll
            for (int mf = 0; mf < 4; mf++) {
                uint32_t ao = aoffs + (uint32_t)(mf * 16 * SMS * 2);
                ldsm4(a_[mf][0], a_[mf][1], a_[mf][2], a_[mf][3], aBase + ao);
            }
            uint32_t bh[4][2];
#pragma unroll
            for (int np = 0; np < 2; np++) {
                uint32_t bo = boffs + (uint32_t)(np * 16 * SMS * 2);
                ldsm4(bh[np * 2][0], bh[np * 2][1], bh[np * 2 + 1][0], bh[np * 2 + 1][1], bBase + bo);
            }
#pragma unroll
            for (int mf = 0; mf < 4; mf++)
#pragma unroll
                for (int nf = 0; nf < 4; nf++)
                    mma16816h(acc[mf][nf], a_[mf], bh[nf]);
        }
    }

#pragma unroll
    for (int mf = 0; mf < 4; mf++) {
#pragma unroll
        for (int nf = 0; nf < 4; nf++) {
            int row0 = rowBase + wr * 64 + mf * 16 + (lane >> 2);
            int col  = colBase + wc * 32 + nf * 8 + 2 * (lane & 3);
            float b0 = bias[col], b1 = bias[col + 1];
#pragma unroll
            for (int half = 0; half < 2; half++) {
                int row = row0 + half * 8;
                if (row < M) {
                    size_t o0 = (size_t)row * N + col;
                    Ch[o0]     = __float2half(acc[mf][nf][half * 2]     + b0);
                    Ch[o0 + 1] = __float2half(acc[mf][nf][half * 2 + 1] + b1);
                }
            }
        }
    }
}

// ---------------- flash attention: 64-query tile, 128 thr, all-fp16, base-2 softmax ----------------
#define AST 72
#define AT_SCALE 0.18033688f   // 0.125 * log2(e)
__global__ void __launch_bounds__(128) attn_mma_kernel(
    const __half* __restrict__ q, const __half* __restrict__ kvh,
    float* __restrict__ o)
{
    __shared__ __half sQ[64 * AST];
    __shared__ __half sK[64 * AST];
    __shared__ __half sV[64 * AST];

    int tid = threadIdx.x, wid = tid >> 5, lane = tid & 31;
    int bh = blockIdx.y, b = bh >> 3, h = bh & 7;
    int qbase = blockIdx.x * 64;
    size_t qoff = ((size_t)b * NTOK + qbase) * CDIM + h * HD;

#pragma unroll
    for (int i = 0; i < 4; i++) {
        int idx = tid + i * 128;
        int r = idx >> 3, c = (idx & 7) << 3;
        *(uint4*)&sQ[r * AST + c] = *(const uint4*)&q[qoff + (size_t)r * CDIM + c];
    }
    __syncthreads();

    uint32_t bQ = (uint32_t)__cvta_generic_to_shared(sQ);
    uint32_t bK = (uint32_t)__cvta_generic_to_shared(sK);
    uint32_t bV = (uint32_t)__cvta_generic_to_shared(sV);

    uint32_t qf[4][4];
    {
        uint32_t qrow = (uint32_t)(wid * 16 + (lane & 15));
#pragma unroll
        for (int kt = 0; kt < 4; kt++) {
            uint32_t off = (qrow * AST + kt * 16 + ((lane >> 4) << 3)) * 2;
            ldsm4(qf[kt][0], qf[kt][1], qf[kt][2], qf[kt][3], bQ + off);
        }
    }

    float acc[8][4];
#pragma unroll
    for (int i = 0; i < 8; i++)
#pragma unroll
        for (int j = 0; j < 4; j++) acc[i][j] = 0.f;
    float m0 = -FLT_MAX, m1 = -FLT_MAX, l0 = 0.f, l1 = 0.f;

    size_t kvoff = (size_t)b * NSR * 1024 + h * HD;
    int cbase = 2 * (lane & 3);

    for (int kb = 0; kb < NSR; kb += 64) {
        __syncthreads();
#pragma unroll
        for (int i = 0; i < 4; i++) {
            int idx = tid + i * 128;
            int r = idx >> 3, c = (idx & 7) << 3;
            int gm = kb + r;
            uint4 z = make_uint4(0u, 0u, 0u, 0u);
            uint4 a0 = z, a1 = z;
            if (gm < NSR) {
                size_t base = kvoff + (size_t)gm * 1024 + c;
                a0 = *(const uint4*)&kvh[base];
                a1 = *(const uint4*)&kvh[base + 512];
            }
            *(uint4*)&sK[r * AST + c] = a0;
            *(uint4*)&sV[r * AST + c] = a1;
        }
        __syncthreads();

        float s_[8][4];
#pragma unroll
        for (int i = 0; i < 8; i++)
#pragma unroll
            for (int j = 0; j < 4; j++) s_[i][j] = 0.f;

#pragma unroll
        for (int kt = 0; kt < 4; kt++) {
#pragma unroll
            for (int np = 0; np < 4; np++) {
                uint32_t brow = (uint32_t)(np * 16 + ((lane >> 4) << 3) + (lane & 7));
                uint32_t boff = (brow * AST + kt * 16 + (((lane >> 3) & 1) << 3)) * 2;
                uint32_t h0, h1, h2, h3;
                ldsm4(h0, h1, h2, h3, bK + boff);
                uint32_t fh0[2] = {h0, h1}, fh1[2] = {h2, h3};
                mma16816h(s_[np * 2],     qf[kt], fh0);
                mma16816h(s_[np * 2 + 1], qf[kt], fh1);
            }
        }

        int valid = NSR - kb; if (valid > 64) valid = 64;
        float rm0 = -FLT_MAX, rm1 = -FLT_MAX;
#pragma unroll
        for (int nt = 0; nt < 8; nt++) {
#pragma unroll
            for (int j = 0; j < 4; j++) s_[nt][j] *= AT_SCALE;
            rm0 = fmaxf(rm0, fmaxf(s_[nt][0], s_[nt][1]));
            rm1 = fmaxf(rm1, fmaxf(s_[nt][2], s_[nt][3]));
        }
        rm0 = fmaxf(rm0, __shfl_xor_sync(0xffffffffu, rm0, 1));
        rm0 = fmaxf(rm0, __shfl_xor_sync(0xffffffffu, rm0, 2));
        rm1 = fmaxf(rm1, __shfl_xor_sync(0xffffffffu, rm1, 1));
        rm1 = fmaxf(rm1, __shfl_xor_sync(0xffffffffu, rm1, 2));
        float nm0 = fmaxf(m0, rm0), nm1 = fmaxf(m1, rm1);
        float corr0 = exp2f(m0 - nm0), corr1 = exp2f(m1 - nm1);
        m0 = nm0; m1 = nm1;

        float sum0 = 0.f, sum1 = 0.f;
#pragma unroll
        for (int nt = 0; nt < 8; nt++) {
            int c0 = nt * 8 + cbase;
            float p0 = (c0     < valid) ? exp2f(s_[nt][0] - nm0) : 0.f;
            float p1 = (c0 + 1 < valid) ? exp2f(s_[nt][1] - nm0) : 0.f;
            float p2 = (c0     < valid) ? exp2f(s_[nt][2] - nm1) : 0.f;
            float p3 = (c0 + 1 < valid) ? exp2f(s_[nt][3] - nm1) : 0.f;
            sum0 += p0 + p1; sum1 += p2 + p3;
            s_[nt][0] = p0; s_[nt][1] = p1; s_[nt][2] = p2; s_[nt][3] = p3;
        }
        sum0 += __shfl_xor_sync(0xffffffffu, sum0, 1);
        sum0 += __shfl_xor_sync(0xffffffffu, sum0, 2);
        sum1 += __shfl_xor_sync(0xffffffffu, sum1, 1);
        sum1 += __shfl_xor_sync(0xffffffffu, sum1, 2);
        l0 = l0 * corr0 + sum0;
        l1 = l1 * corr1 + sum1;

#pragma unroll
        for (int nt = 0; nt < 8; nt++) {
            acc[nt][0] *= corr0; acc[nt][1] *= corr0;
            acc[nt][2] *= corr1; acc[nt][3] *= corr1;
        }

#pragma unroll
        for (int kt = 0; kt < 4; kt++) {
            uint32_t ph[4];
#pragma unroll
            for (int q2 = 0; q2 < 2; q2++) {
                int nt = 2 * kt + q2;
                ph[q2 * 2]     = packh2(s_[nt][0], s_[nt][1]);
                ph[q2 * 2 + 1] = packh2(s_[nt][2], s_[nt][3]);
            }
            int l8 = lane >> 3, li = lane & 7;
#pragma unroll
            for (int np = 0; np < 4; np++) {
                uint32_t vrow = (uint32_t)(kt * 16 + ((l8 & 1) << 3) + li);
                uint32_t vcol = (uint32_t)(np * 16 + ((l8 >> 1) << 3));
                uint32_t voff = (vrow * AST + vcol) * 2;
                uint32_t h0, h1, h2, h3;
                ldsm4t(h0, h1, h2, h3, bV + voff);
                uint32_t fh0[2] = {h0, h1}, fh1[2] = {h2, h3};
                mma16816h(acc[np * 2],     ph, fh0);
                mma16816h(acc[np * 2 + 1], ph, fh1);
            }
        }
    }

    float inv0 = 1.f / l0, inv1 = 1.f / l1;
    int r0 = qbase + wid * 16 + (lane >> 2);
    size_t ob0 = ((size_t)b * NTOK + r0) * CDIM + h * HD;
    size_t ob1 = ob0 + (size_t)8 * CDIM;
#pragma unroll
    for (int nt = 0; nt < 8; nt++) {
        int cc = nt * 8 + cbase;
        o[ob0 + cc]     = acc[nt][0] * inv0;
        o[ob0 + cc + 1] = acc[nt][1] * inv0;
        o[ob1 + cc]     = acc[nt][2] * inv1;
        o[ob1 + cc + 1] = acc[nt][3] * inv1;
    }
}

// ---------------- trilinear upsample of V + LN + add o -> fp16 hi/lo ----------------
__global__ void __launch_bounds__(256) ups_ln_add_kernel(
    const float* __restrict__ kv, const float* __restrict__ ob,
    const float* __restrict__ g, const float* __restrict__ beta,
    __half* __restrict__ yh, __half* __restrict__ yl)
{
    int bn = blockIdx.x;
    int b = bn / NTOK, n = bn % NTOK;
    int d = n / 400, hh = (n / 20) % 20, ww = n % 20;
    float sd = d  * 0.5f - 0.25f; int fd = (int)floorf(sd); float wdz = sd - (float)fd;
    float sh = hh * 0.5f - 0.25f; int fh = (int)floorf(sh); float why = sh - (float)fh;
    float sw = ww * 0.5f - 0.25f; int fw = (int)floorf(sw); float wwx = sw - (float)fw;
    int dz0 = fd < 0 ? 0 : fd; int dz1 = (fd + 1) > 9 ? 9 : (fd + 1);
    int hy0 = fh < 0 ? 0 : fh; int hy1 = (fh + 1) > 9 ? 9 : (fh + 1);
    int wx0 = fw < 0 ? 0 : fw; int wx1 = (fw + 1) > 9 ? 9 : (fw + 1);
    int midx[8]; float wt8[8];
    {
        int zz[2] = {dz0, dz1};  float wz[2] = {1.f - wdz, wdz};
        int yy[2] = {hy0, hy1};  float wy[2] = {1.f - why, why};
        int xx[2] = {wx0, wx1};  float wx[2] = {1.f - wwx, wwx};
        int t = 0;
        for (int a = 0; a < 2; a++)
            for (int b2 = 0; b2 < 2; b2++)
                for (int c2 = 0; c2 < 2; c2++) {
                    midx[t] = zz[a] * 100 + yy[b2] * 10 + xx[c2];
                    wt8[t]  = wz[a] * wy[b2] * wx[c2]; t++;
                }
    }
    __shared__ float vals[CDIM];
    __shared__ float red[18];
    size_t kvb = (size_t)b * NSR * 1024 + 512;
    float loc[2];
#pragma unroll
    for (int ci = 0; ci < 2; ci++) {
        int c = threadIdx.x + ci * 256;
        float acc = 0.f;
#pragma unroll
        for (int t = 0; t < 8; t++)
            acc += wt8[t] * kv[kvb + (size_t)midx[t] * 1024 + c];
        vals[c] = acc; loc[ci] = acc;
    }
    float s = loc[0] + loc[1], sq = loc[0] * loc[0] + loc[1] * loc[1];
#pragma unroll
    for (int o2 = 16; o2 > 0; o2 >>= 1) {
        s  += __shfl_down_sync(0xffffffffu, s,  o2);
        sq += __shfl_down_sync(0xffffffffu, sq, o2);
    }
    int w = threadIdx.x >> 5;
    if ((threadIdx.x & 31) == 0) { red[w] = s; red[8 + w] = sq; }
    __syncthreads();
    if (threadIdx.x == 0) {
        float a = 0.f, b2 = 0.f;
        for (int i = 0; i < 8; i++) { a += red[i]; b2 += red[8 + i]; }
        red[16] = a; red[17] = b2;
    }
    __syncthreads();
    float mean = red[16] * (1.f / CDIM);
    float var  = red[17] * (1.f / CDIM) - mean * mean;
    float inv  = rsqrtf(var + 1e-6f);
#pragma unroll
    for (int ci = 0; ci < 2; ci++) {
        int c = threadIdx.x + ci * 256;
        size_t oidx = ((size_t)b * NTOK + n) * CDIM + c;
        float v = ob[oidx] + (vals[c] - mean) * inv * g[c] + beta[c];
        __half hb = __float2half(v);
        yh[oidx] = hb;
        yl[oidx] = __float2half(v - __half2float(hb));
    }
}

// ---------------- launch ----------------
extern "C" void kernel_launch(void* const* d_in, const int* in_sizes, int n_in,
                              void* d_out, int out_size)
{
    const float* x      = (const float*)d_in[0];
    const float* Wq     = (const float*)d_in[1];
    const float* bq     = (const float*)d_in[2];
    const float* Wkv    = (const float*)d_in[3];
    const float* bkv    = (const float*)d_in[4];
    const float* srw    = (const float*)d_in[5];
    const float* srb    = (const float*)d_in[6];
    const float* srg    = (const float*)d_in[7];
    const float* srbeta = (const float*)d_in[8];
    const float* upg    = (const float*)d_in[9];
    const float* upbeta = (const float*)d_in[10];
    const float* Wp     = (const float*)d_in[11];
    const float* bp     = (const float*)d_in[12];
    float* out = (float*)d_out;

    float *kvb, *ob;
    __half *yh, *yl, *xrh, *xrl, *qh, *kvh, *wqt, *wkvt, *wpt;
    cudaGetSymbolAddress((void**)&kvb, g_kv);
    cudaGetSymbolAddress((void**)&ob,  g_o);
    cudaGetSymbolAddress((void**)&yh,  g_yh);
    cudaGetSymbolAddress((void**)&yl,  g_yl);
    cudaGetSymbolAddress((void**)&qh,  g_qh);
    cudaGetSymbolAddress((void**)&kvh, g_kvh);
    cudaGetSymbolAddress((void**)&xrh, g_xrh);
    cudaGetSymbolAddress((void**)&xrl, g_xrl);
    cudaGetSymbolAddress((void**)&wqt, g_wqt);
    cudaGetSymbolAddress((void**)&wkvt, g_wkvt);
    cudaGetSymbolAddress((void**)&wpt, g_wpt);

    wsplit_all_kernel<<<1024, 256>>>(Wq, Wkv, Wp, wqt, wkvt, wpt);                 // 1
    conv_ln_kernel<<<BATCH * NSR, 256>>>(x, srw, srb, srg, srbeta, xrh, xrl);      // 2

    // kv = xr @ Wkv + bkv -> f32 (upsample) + fp16 (attention)
    gemm2h_kernel<<<dim3(1024 / 128, (BATCH * NSR + 127) / 128), 256>>>(           // 3
        xrh, xrl, wkvt, bkv, kvb, kvh, BATCH * NSR, 1024);
    // q = cvt16(x) @ Wq + bq -> fp16 (fused conversion)
    gemm1hf_kernel<<<dim3(512 / 128, (BATCH * NTOK) / 128), 256>>>(                // 4
        x, wqt, bq, qh, BATCH * NTOK, 512);

    attn_mma_kernel<<<dim3(NTOK / 64, BATCH * NHEADS), 128>>>(qh, kvh, ob);        // 5

    ups_ln_add_kernel<<<BATCH * NTOK, 256>>>(kvb, ob, upg, upbeta, yh, yl);        // 6

    // out = (yh+yl) @ Wp + bp -> f32 (2-term fp16)
    gemm2h_kernel<<<dim3(512 / 128, (BATCH * NTOK) / 128), 256>>>(                 // 7
        yh, yl, wpt, bp, out, (__half*)nullptr, BATCH * NTOK, 512);
}

// round 15
// speedup vs baseline: 1.1307x; 1.0174x over previous
#include <cuda_runtime.h>
#include <cuda_bf16.h>
#include <cuda_fp16.h>
#include <math.h>
#include <float.h>
#include <stdint.h>

#define BATCH 2
#define NTOK  8000
#define CDIM  512
#define NSR   1000
#define NHEADS 8
#define HD    64

__device__ float g_kv[BATCH * NSR * 2 * CDIM];
__device__ float g_o [BATCH * NTOK * CDIM];
__device__ __half g_yh [BATCH * NTOK * CDIM];
__device__ __half g_yl [BATCH * NTOK * CDIM];
__device__ __half g_qh [BATCH * NTOK * CDIM];
__device__ __half g_kvh[BATCH * NSR * 2 * CDIM];
__device__ __half g_xrh[BATCH * NSR * CDIM];
__device__ __half g_xrl[BATCH * NSR * CDIM];
__device__ __half g_wqt [CDIM * CDIM];
__device__ __half g_wkvt[2 * CDIM * CDIM];
__device__ __half g_wpt [CDIM * CDIM];

// ---------------- ptx helpers ----------------
__device__ __forceinline__ void ldsm4(uint32_t& r0, uint32_t& r1, uint32_t& r2, uint32_t& r3,
                                      uint32_t addr)
{
    asm volatile("ldmatrix.sync.aligned.m8n8.x4.shared.b16 {%0,%1,%2,%3}, [%4];"
                 : "=r"(r0), "=r"(r1), "=r"(r2), "=r"(r3) : "r"(addr));
}
__device__ __forceinline__ void ldsm4t(uint32_t& r0, uint32_t& r1, uint32_t& r2, uint32_t& r3,
                                       uint32_t addr)
{
    asm volatile("ldmatrix.sync.aligned.m8n8.x4.trans.shared.b16 {%0,%1,%2,%3}, [%4];"
                 : "=r"(r0), "=r"(r1), "=r"(r2), "=r"(r3) : "r"(addr));
}
__device__ __forceinline__ void mma16816h(float* c, const uint32_t* a, const uint32_t* b)
{
    asm volatile("mma.sync.aligned.m16n8k16.row.col.f32.f16.f16.f32 "
                 "{%0,%1,%2,%3}, {%4,%5,%6,%7}, {%8,%9}, {%0,%1,%2,%3};"
                 : "+f"(c[0]), "+f"(c[1]), "+f"(c[2]), "+f"(c[3])
                 : "r"(a[0]), "r"(a[1]), "r"(a[2]), "r"(a[3]), "r"(b[0]), "r"(b[1]));
}
__device__ __forceinline__ uint32_t packh2(float a, float b) {
    __half2 t = __floats2half2_rn(a, b);
    return *(uint32_t*)&t;
}
__device__ __forceinline__ void cpa16(uint32_t dst, const void* src) {
    asm volatile("cp.async.cg.shared.global [%0], [%1], 16;" :: "r"(dst), "l"(src) : "memory");
}
__device__ __forceinline__ void cpa16z(uint32_t dst, const void* src, int sz) {
    asm volatile("cp.async.cg.shared.global [%0], [%1], 16, %2;"
                 :: "r"(dst), "l"(src), "r"(sz) : "memory");
}
#define CPA_COMMIT() asm volatile("cp.async.commit_group;" ::: "memory")
#define CPA_WAIT1()  asm volatile("cp.async.wait_group 1;" ::: "memory")
#define CPA_WAIT0()  asm volatile("cp.async.wait_group 0;" ::: "memory")

// ---------------- transpose ALL weights to fp16 [N][K] in one launch ----------------
__global__ void __launch_bounds__(256) wsplit_all_kernel(
    const float* __restrict__ Wq, const float* __restrict__ Wkv,
    const float* __restrict__ Wp,
    __half* __restrict__ qt, __half* __restrict__ kt, __half* __restrict__ pt)
{
    __shared__ float t[32][33];
    int tb = blockIdx.x;
    const float* W; __half* T; int N, nb, kb;
    if (tb < 256)      { W = Wq;  T = qt; N = 512;  int tt = tb;       nb = (tt & 15) * 32; kb = (tt >> 4) * 32; }
    else if (tb < 768) { W = Wkv; T = kt; N = 1024; int tt = tb - 256; nb = (tt & 31) * 32; kb = (tt >> 5) * 32; }
    else               { W = Wp;  T = pt; N = 512;  int tt = tb - 768; nb = (tt & 15) * 32; kb = (tt >> 4) * 32; }
    const int K = 512;
    int tx = threadIdx.x & 31, ty = threadIdx.x >> 5;
#pragma unroll
    for (int i = ty; i < 32; i += 8)
        t[i][tx] = W[(size_t)(kb + i) * N + nb + tx];
    __syncthreads();
#pragma unroll
    for (int i = ty; i < 32; i += 8)
        T[(size_t)(nb + i) * K + kb + tx] = __float2half(t[tx][i]);
}

// ---------------- conv3d depthwise (3,s2,p1) + bias + LN -> fp16 hi/lo ----------------
__global__ void __launch_bounds__(256) conv_ln_kernel(
    const float* __restrict__ x, const float* __restrict__ srw,
    const float* __restrict__ srb, const float* __restrict__ g,
    const float* __restrict__ beta,
    __half* __restrict__ xrh, __half* __restrict__ xrl)
{
    int bp = blockIdx.x;
    int b = bp / NSR, opos = bp % NSR;
    int od = opos / 100, oh = (opos / 10) % 10, ow = opos % 10;
    __shared__ float vals[CDIM];
    __shared__ float red[18];
    float loc[2];
#pragma unroll
    for (int ci = 0; ci < 2; ci++) {
        int c = threadIdx.x + ci * 256;
        float acc = srb[c];
#pragma unroll
        for (int kd = 0; kd < 3; kd++) {
            int id = od * 2 - 1 + kd;
            if ((unsigned)id >= 20u) continue;
#pragma unroll
            for (int kh = 0; kh < 3; kh++) {
                int ih = oh * 2 - 1 + kh;
                if ((unsigned)ih >= 20u) continue;
#pragma unroll
                for (int kw = 0; kw < 3; kw++) {
                    int iw = ow * 2 - 1 + kw;
                    if ((unsigned)iw >= 20u) continue;
                    acc += x[((size_t)b * NTOK + id * 400 + ih * 20 + iw) * CDIM + c] *
                           srw[c * 27 + kd * 9 + kh * 3 + kw];
                }
            }
        }
        vals[c] = acc; loc[ci] = acc;
    }
    float s = loc[0] + loc[1], sq = loc[0] * loc[0] + loc[1] * loc[1];
#pragma unroll
    for (int o2 = 16; o2 > 0; o2 >>= 1) {
        s  += __shfl_down_sync(0xffffffffu, s,  o2);
        sq += __shfl_down_sync(0xffffffffu, sq, o2);
    }
    int w = threadIdx.x >> 5;
    if ((threadIdx.x & 31) == 0) { red[w] = s; red[8 + w] = sq; }
    __syncthreads();
    if (threadIdx.x == 0) {
        float a = 0.f, b2 = 0.f;
        for (int i = 0; i < 8; i++) { a += red[i]; b2 += red[8 + i]; }
        red[16] = a; red[17] = b2;
    }
    __syncthreads();
    float mean = red[16] * (1.f / CDIM);
    float var  = red[17] * (1.f / CDIM) - mean * mean;
    float inv  = rsqrtf(var + 1e-6f);
#pragma unroll
    for (int ci = 0; ci < 2; ci++) {
        int c = threadIdx.x + ci * 256;
        float v = (vals[c] - mean) * inv * g[c] + beta[c];
        size_t idx = ((size_t)b * NSR + opos) * CDIM + c;
        __half hh = __float2half(v);
        xrh[idx] = hh;
        xrl[idx] = __float2half(v - __half2float(hh));
    }
}

#define SMS 72   // row stride for BK=64 tiles (144B: ldmatrix conflict-free)
#define GT_BYTES (128 * SMS * 2)        // 18432 B per 128x64 fp16 tile
#define G2_STAGE (3 * GT_BYTES)         // Ah+Al+B per stage
#define G2_SMEM  (2 * G2_STAGE)         // 110592 B

// ---------------- fp16 2-term GEMM (BK=64, cp.async double-buffered) ----------------
__global__ void __launch_bounds__(256, 2) gemm2h_kernel(
    const __half* __restrict__ Ah, const __half* __restrict__ Al,
    const __half* __restrict__ B, const float* __restrict__ bias,
    float* __restrict__ C, __half* __restrict__ Ch, int M, int N)
{
    extern __shared__ __align__(16) __half g2sm[];
    uint32_t sbase = (uint32_t)__cvta_generic_to_shared(g2sm);

    int tid = threadIdx.x, wid = tid >> 5, lane = tid & 31;
    int wr = wid >> 2, wc = wid & 3;
    int rowBase = blockIdx.y * 128, colBase = blockIdx.x * 128;

    float acc[4][4][4];
#pragma unroll
    for (int i = 0; i < 4; i++)
#pragma unroll
        for (int j = 0; j < 4; j++)
#pragma unroll
            for (int k = 0; k < 4; k++) acc[i][j][k] = 0.f;

#define G2_LOAD(st, k0) do { \
        uint32_t stb = sbase + (uint32_t)((st) * G2_STAGE); \
        _Pragma("unroll") \
        for (int it = 0; it < 4; it++) { \
            int idx = tid + it * 256; \
            int r = idx >> 3, c = idx & 7; \
            int ar = rowBase + r; if (ar > M - 1) ar = M - 1; \
            int br = colBase + r; \
            size_t aoff = (size_t)ar * 512 + (k0) + c * 8; \
            size_t boff = (size_t)br * 512 + (k0) + c * 8; \
            uint32_t so = (uint32_t)((r * SMS + c * 8) * 2); \
            cpa16(stb + so,                Ah + aoff); \
            cpa16(stb + GT_BYTES + so,     Al + aoff); \
            cpa16(stb + 2 * GT_BYTES + so, B  + boff); \
        } \
    } while (0)

    G2_LOAD(0, 0);
    CPA_COMMIT();

    for (int ck = 0; ck < 8; ck++) {
        if (ck + 1 < 8) { G2_LOAD((ck + 1) & 1, (ck + 1) * 64); CPA_COMMIT(); CPA_WAIT1(); }
        else            { CPA_WAIT0(); }
        __syncthreads();

        uint32_t stb = sbase + (uint32_t)((ck & 1) * G2_STAGE);
        uint32_t aBaseH = stb, aBaseL = stb + GT_BYTES, bBase = stb + 2 * GT_BYTES;

#pragma unroll
        for (int ks = 0; ks < 64; ks += 16) {
            uint32_t aoffs = (uint32_t)(((wr * 64 + (lane & 15)) * SMS + ks + ((lane >> 4) << 3)) * 2);
            uint32_t boffs = (uint32_t)(((wc * 32 + ((lane >> 4) << 3) + (lane & 7)) * SMS + ks + (((lane >> 3) & 1) << 3)) * 2);

            uint32_t ah[4][4], al[4][4];
#pragma unroll
            for (int mf = 0; mf < 4; mf++) {
                uint32_t ao = aoffs + (uint32_t)(mf * 16 * SMS * 2);
                ldsm4(ah[mf][0], ah[mf][1], ah[mf][2], ah[mf][3], aBaseH + ao);
                ldsm4(al[mf][0], al[mf][1], al[mf][2], al[mf][3], aBaseL + ao);
            }
            uint32_t bh[4][2];
#pragma unroll
            for (int np = 0; np < 2; np++) {
                uint32_t bo = boffs + (uint32_t)(np * 16 * SMS * 2);
                ldsm4(bh[np * 2][0], bh[np * 2][1], bh[np * 2 + 1][0], bh[np * 2 + 1][1], bBase + bo);
            }
#pragma unroll
            for (int mf = 0; mf < 4; mf++)
#pragma unroll
                for (int nf = 0; nf < 4; nf++) {
                    mma16816h(acc[mf][nf], ah[mf], bh[nf]);
                    mma16816h(acc[mf][nf], al[mf], bh[nf]);
                }
        }
        __syncthreads();
    }
#undef G2_LOAD

#pragma unroll
    for (int mf = 0; mf < 4; mf++) {
#pragma unroll
        for (int nf = 0; nf < 4; nf++) {
            int row0 = rowBase + wr * 64 + mf * 16 + (lane >> 2);
            int col  = colBase + wc * 32 + nf * 8 + 2 * (lane & 3);
            float b0 = bias[col], b1 = bias[col + 1];
#pragma unroll
            for (int half = 0; half < 2; half++) {
                int row = row0 + half * 8;
                if (row < M) {
                    float v0 = acc[mf][nf][half * 2]     + b0;
                    float v1 = acc[mf][nf][half * 2 + 1] + b1;
                    size_t o0 = (size_t)row * N + col;
                    if (C) { C[o0] = v0; C[o0 + 1] = v1; }
                    if (Ch) {
                        Ch[o0]     = __float2half(v0);
                        Ch[o0 + 1] = __float2half(v1);
                    }
                }
            }
        }
    }
}

// ---------------- fp16 1-term GEMM (BK=64) with fused f32->fp16 A conversion ----------------
__global__ void __launch_bounds__(256, 2) gemm1hf_kernel(
    const float* __restrict__ A, const __half* __restrict__ B,
    const float* __restrict__ bias, __half* __restrict__ Ch, int M, int N)
{
    __shared__ __half sA[128 * SMS], sB[128 * SMS];

    int tid = threadIdx.x, wid = tid >> 5, lane = tid & 31;
    int wr = wid >> 2, wc = wid & 3;
    int rowBase = blockIdx.y * 128, colBase = blockIdx.x * 128;

    float acc[4][4][4];
#pragma unroll
    for (int i = 0; i < 4; i++)
#pragma unroll
        for (int j = 0; j < 4; j++)
#pragma unroll
            for (int k = 0; k < 4; k++) acc[i][j][k] = 0.f;

    uint32_t aBase = (uint32_t)__cvta_generic_to_shared(sA);
    uint32_t bBase = (uint32_t)__cvta_generic_to_shared(sB);

    for (int k0 = 0; k0 < 512; k0 += 64) {
        __syncthreads();
#pragma unroll
        for (int it = 0; it < 4; it++) {
            int idx = tid + it * 256;
            int r = idx >> 3, c = idx & 7;
            int ar = rowBase + r; if (ar > M - 1) ar = M - 1;
            int br = colBase + r;
            size_t aoff = (size_t)ar * 512 + k0 + c * 8;
            size_t boff = (size_t)br * 512 + k0 + c * 8;
            int soff = r * SMS + c * 8;
            float4 f0 = *(const float4*)&A[aoff];
            float4 f1 = *(const float4*)&A[aoff + 4];
            __half2 h0 = __floats2half2_rn(f0.x, f0.y);
            __half2 h1 = __floats2half2_rn(f0.z, f0.w);
            __half2 h2 = __floats2half2_rn(f1.x, f1.y);
            __half2 h3 = __floats2half2_rn(f1.z, f1.w);
            uint4 pk;
            pk.x = *(uint32_t*)&h0; pk.y = *(uint32_t*)&h1;
            pk.z = *(uint32_t*)&h2; pk.w = *(uint32_t*)&h3;
            *(uint4*)&sA[soff] = pk;
            *(uint4*)&sB[soff] = *(const uint4*)&B[boff];
        }
        __syncthreads();

#pragma unroll
        for (int ks = 0; ks < 64; ks += 16) {
            uint32_t aoffs = (uint32_t)(((wr * 64 + (lane & 15)) * SMS + ks + ((lane >> 4) << 3)) * 2);
            uint32_t boffs = (uint32_t)(((wc * 32 + ((lane >> 4) << 3) + (lane & 7)) * SMS + ks + (((lane >> 3) & 1) << 3)) * 2);

            uint32_t a_[4][4];
#pragma unroll
            for (int mf = 0; mf < 4; mf++) {
                uint32_t ao = aoffs + (uint32_t)(mf * 16 * SMS * 2);
                ldsm4(a_[mf][0], a_[mf][1], a_[mf][2], a_[mf][3], aBase + ao);
            }
            uint32_t bh[4][2];
#pragma unroll
            for (int np = 0; np < 2; np++) {
                uint32_t bo = boffs + (uint32_t)(np * 16 * SMS * 2);
                ldsm4(bh[np * 2][0], bh[np * 2][1], bh[np * 2 + 1][0], bh[np * 2 + 1][1], bBase + bo);
            }
#pragma unroll
            for (int mf = 0; mf < 4; mf++)
#pragma unroll
                for (int nf = 0; nf < 4; nf++)
                    mma16816h(acc[mf][nf], a_[mf], bh[nf]);
        }
    }

#pragma unroll
    for (int mf = 0; mf < 4; mf++) {
#pragma unroll
        for (int nf = 0; nf < 4; nf++) {
            int row0 = rowBase + wr * 64 + mf * 16 + (lane >> 2);
            int col  = colBase + wc * 32 + nf * 8 + 2 * (lane & 3);
            float b0 = bias[col], b1 = bias[col + 1];
#pragma unroll
            for (int half = 0; half < 2; half++) {
                int row = row0 + half * 8;
                if (row < M) {
                    size_t o0 = (size_t)row * N + col;
                    Ch[o0]     = __float2half(acc[mf][nf][half * 2]     + b0);
                    Ch[o0 + 1] = __float2half(acc[mf][nf][half * 2 + 1] + b1);
                }
            }
        }
    }
}

// ---------------- flash attention: 64-q tile, cp.async double-buffered KV ----------------
#define AST 72
#define AT_TILE_BYTES (64 * AST * 2)    // 9216 B
#define AT_SCALE 0.18033688f            // 0.125 * log2(e)
__global__ void __launch_bounds__(128) attn_mma_kernel(
    const __half* __restrict__ q, const __half* __restrict__ kvh,
    float* __restrict__ o)
{
    __shared__ __half sQ[64 * AST];
    __shared__ __half sKV[4 * 64 * AST];   // 2 stages x (K,V)

    int tid = threadIdx.x, wid = tid >> 5, lane = tid & 31;
    int bh = blockIdx.y, b = bh >> 3, h = bh & 7;
    int qbase = blockIdx.x * 64;
    size_t qoff = ((size_t)b * NTOK + qbase) * CDIM + h * HD;

#pragma unroll
    for (int i = 0; i < 4; i++) {
        int idx = tid + i * 128;
        int r = idx >> 3, c = (idx & 7) << 3;
        *(uint4*)&sQ[r * AST + c] = *(const uint4*)&q[qoff + (size_t)r * CDIM + c];
    }
    __syncthreads();

    uint32_t bQ   = (uint32_t)__cvta_generic_to_shared(sQ);
    uint32_t kvBs = (uint32_t)__cvta_generic_to_shared(sKV);

    uint32_t qf[4][4];
    {
        uint32_t qrow = (uint32_t)(wid * 16 + (lane & 15));
#pragma unroll
        for (int kt = 0; kt < 4; kt++) {
            uint32_t off = (qrow * AST + kt * 16 + ((lane >> 4) << 3)) * 2;
            ldsm4(qf[kt][0], qf[kt][1], qf[kt][2], qf[kt][3], bQ + off);
        }
    }

    float acc[8][4];
#pragma unroll
    for (int i = 0; i < 8; i++)
#pragma unroll
        for (int j = 0; j < 4; j++) acc[i][j] = 0.f;
    float m0 = -FLT_MAX, m1 = -FLT_MAX, l0 = 0.f, l1 = 0.f;

    size_t kvoff = (size_t)b * NSR * 1024 + h * HD;
    int cbase = 2 * (lane & 3);

#define AT_LOAD(st, kb) do { \
        uint32_t stb = kvBs + (uint32_t)((st) * 2 * AT_TILE_BYTES); \
        _Pragma("unroll") \
        for (int i = 0; i < 4; i++) { \
            int idx = tid + i * 128; \
            int r = idx >> 3, c = (idx & 7) << 3; \
            int gm = (kb) + r; \
            int sz = (gm < NSR) ? 16 : 0; \
            int gmc = (gm < NSR) ? gm : (NSR - 1); \
            const __half* src = kvh + kvoff + (size_t)gmc * 1024 + c; \
            uint32_t so = (uint32_t)((r * AST + c) * 2); \
            cpa16z(stb + so,                 src,       sz); \
            cpa16z(stb + AT_TILE_BYTES + so, src + 512, sz); \
        } \
    } while (0)

    AT_LOAD(0, 0);
    CPA_COMMIT();

    for (int it = 0; it < 16; it++) {
        if (it + 1 < 16) { AT_LOAD((it + 1) & 1, (it + 1) * 64); CPA_COMMIT(); CPA_WAIT1(); }
        else             { CPA_WAIT0(); }
        __syncthreads();

        uint32_t stb = kvBs + (uint32_t)((it & 1) * 2 * AT_TILE_BYTES);
        uint32_t bK = stb, bV = stb + AT_TILE_BYTES;
        int kb = it * 64;

        float s_[8][4];
#pragma unroll
        for (int i = 0; i < 8; i++)
#pragma unroll
            for (int j = 0; j < 4; j++) s_[i][j] = 0.f;

#pragma unroll
        for (int kt = 0; kt < 4; kt++) {
#pragma unroll
            for (int np = 0; np < 4; np++) {
                uint32_t brow = (uint32_t)(np * 16 + ((lane >> 4) << 3) + (lane & 7));
                uint32_t boff = (brow * AST + kt * 16 + (((lane >> 3) & 1) << 3)) * 2;
                uint32_t h0, h1, h2, h3;
                ldsm4(h0, h1, h2, h3, bK + boff);
                uint32_t fh0[2] = {h0, h1}, fh1[2] = {h2, h3};
                mma16816h(s_[np * 2],     qf[kt], fh0);
                mma16816h(s_[np * 2 + 1], qf[kt], fh1);
            }
        }

        int valid = NSR - kb; if (valid > 64) valid = 64;
        float rm0 = -FLT_MAX, rm1 = -FLT_MAX;
#pragma unroll
        for (int nt = 0; nt < 8; nt++) {
#pragma unroll
            for (int j = 0; j < 4; j++) s_[nt][j] *= AT_SCALE;
            rm0 = fmaxf(rm0, fmaxf(s_[nt][0], s_[nt][1]));
            rm1 = fmaxf(rm1, fmaxf(s_[nt][2], s_[nt][3]));
        }
        rm0 = fmaxf(rm0, __shfl_xor_sync(0xffffffffu, rm0, 1));
        rm0 = fmaxf(rm0, __shfl_xor_sync(0xffffffffu, rm0, 2));
        rm1 = fmaxf(rm1, __shfl_xor_sync(0xffffffffu, rm1, 1));
        rm1 = fmaxf(rm1, __shfl_xor_sync(0xffffffffu, rm1, 2));
        float nm0 = fmaxf(m0, rm0), nm1 = fmaxf(m1, rm1);
        float corr0 = exp2f(m0 - nm0), corr1 = exp2f(m1 - nm1);
        m0 = nm0; m1 = nm1;

        float sum0 = 0.f, sum1 = 0.f;
#pragma unroll
        for (int nt = 0; nt < 8; nt++) {
            int c0 = nt * 8 + cbase;
            float p0 = (c0     < valid) ? exp2f(s_[nt][0] - nm0) : 0.f;
            float p1 = (c0 + 1 < valid) ? exp2f(s_[nt][1] - nm0) : 0.f;
            float p2 = (c0     < valid) ? exp2f(s_[nt][2] - nm1) : 0.f;
            float p3 = (c0 + 1 < valid) ? exp2f(s_[nt][3] - nm1) : 0.f;
            sum0 += p0 + p1; sum1 += p2 + p3;
            s_[nt][0] = p0; s_[nt][1] = p1; s_[nt][2] = p2; s_[nt][3] = p3;
        }
        sum0 += __shfl_xor_sync(0xffffffffu, sum0, 1);
        sum0 += __shfl_xor_sync(0xffffffffu, sum0, 2);
        sum1 += __shfl_xor_sync(0xffffffffu, sum1, 1);
        sum1 += __shfl_xor_sync(0xffffffffu, sum1, 2);
        l0 = l0 * corr0 + sum0;
        l1 = l1 * corr1 + sum1;

#pragma unroll
        for (int nt = 0; nt < 8; nt++) {
            acc[nt][0] *= corr0; acc[nt][1] *= corr0;
            acc[nt][2] *= corr1; acc[nt][3] *= corr1;
        }

#pragma unroll
        for (int kt = 0; kt < 4; kt++) {
            uint32_t ph[4];
#pragma unroll
            for (int q2 = 0; q2 < 2; q2++) {
                int nt = 2 * kt + q2;
                ph[q2 * 2]     = packh2(s_[nt][0], s_[nt][1]);
                ph[q2 * 2 + 1] = packh2(s_[nt][2], s_[nt][3]);
            }
            int l8 = lane >> 3, li = lane & 7;
#pragma unroll
            for (int np = 0; np < 4; np++) {
                uint32_t vrow = (uint32_t)(kt * 16 + ((l8 & 1) << 3) + li);
                uint32_t vcol = (uint32_t)(np * 16 + ((l8 >> 1) << 3));
                uint32_t voff = (vrow * AST + vcol) * 2;
                uint32_t h0, h1, h2, h3;
                ldsm4t(h0, h1, h2, h3, bV + voff);
                uint32_t fh0[2] = {h0, h1}, fh1[2] = {h2, h3};
                mma16816h(acc[np * 2],     ph, fh0);
                mma16816h(acc[np * 2 + 1], ph, fh1);
            }
        }
        __syncthreads();
    }
#undef AT_LOAD

    float inv0 = 1.f / l0, inv1 = 1.f / l1;
    int r0 = qbase + wid * 16 + (lane >> 2);
    size_t ob0 = ((size_t)b * NTOK + r0) * CDIM + h * HD;
    size_t ob1 = ob0 + (size_t)8 * CDIM;
#pragma unroll
    for (int nt = 0; nt < 8; nt++) {
        int cc = nt * 8 + cbase;
        o[ob0 + cc]     = acc[nt][0] * inv0;
        o[ob0 + cc + 1] = acc[nt][1] * inv0;
        o[ob1 + cc]     = acc[nt][2] * inv1;
        o[ob1 + cc + 1] = acc[nt][3] * inv1;
    }
}

// ---------------- trilinear upsample of V + LN + add o -> fp16 hi/lo ----------------
__global__ void __launch_bounds__(256) ups_ln_add_kernel(
    const float* __restrict__ kv, const float* __restrict__ ob,
    const float* __restrict__ g, const float* __restrict__ beta,
    __half* __restrict__ yh, __half* __restrict__ yl)
{
    int bn = blockIdx.x;
    int b = bn / NTOK, n = bn % NTOK;
    int d = n / 400, hh = (n / 20) % 20, ww = n % 20;
    float sd = d  * 0.5f - 0.25f; int fd = (int)floorf(sd); float wdz = sd - (float)fd;
    float sh = hh * 0.5f - 0.25f; int fh = (int)floorf(sh); float why = sh - (float)fh;
    float sw = ww * 0.5f - 0.25f; int fw = (int)floorf(sw); float wwx = sw - (float)fw;
    int dz0 = fd < 0 ? 0 : fd; int dz1 = (fd + 1) > 9 ? 9 : (fd + 1);
    int hy0 = fh < 0 ? 0 : fh; int hy1 = (fh + 1) > 9 ? 9 : (fh + 1);
    int wx0 = fw < 0 ? 0 : fw; int wx1 = (fw + 1) > 9 ? 9 : (fw + 1);
    int midx[8]; float wt8[8];
    {
        int zz[2] = {dz0, dz1};  float wz[2] = {1.f - wdz, wdz};
        int yy[2] = {hy0, hy1};  float wy[2] = {1.f - why, why};
        int xx[2] = {wx0, wx1};  float wx[2] = {1.f - wwx, wwx};
        int t = 0;
        for (int a = 0; a < 2; a++)
            for (int b2 = 0; b2 < 2; b2++)
                for (int c2 = 0; c2 < 2; c2++) {
                    midx[t] = zz[a] * 100 + yy[b2] * 10 + xx[c2];
                    wt8[t]  = wz[a] * wy[b2] * wx[c2]; t++;
                }
    }
    __shared__ float vals[CDIM];
    __shared__ float red[18];
    size_t kvb = (size_t)b * NSR * 1024 + 512;
    float loc[2];
#pragma unroll
    for (int ci = 0; ci < 2; ci++) {
        int c = threadIdx.x + ci * 256;
        float acc = 0.f;
#pragma unroll
        for (int t = 0; t < 8; t++)
            acc += wt8[t] * kv[kvb + (size_t)midx[t] * 1024 + c];
        vals[c] = acc; loc[ci] = acc;
    }
    float s = loc[0] + loc[1], sq = loc[0] * loc[0] + loc[1] * loc[1];
#pragma unroll
    for (int o2 = 16; o2 > 0; o2 >>= 1) {
        s  += __shfl_down_sync(0xffffffffu, s,  o2);
        sq += __shfl_down_sync(0xffffffffu, sq, o2);
    }
    int w = threadIdx.x >> 5;
    if ((threadIdx.x & 31) == 0) { red[w] = s; red[8 + w] = sq; }
    __syncthreads();
    if (threadIdx.x == 0) {
        float a = 0.f, b2 = 0.f;
        for (int i = 0; i < 8; i++) { a += red[i]; b2 += red[8 + i]; }
        red[16] = a; red[17] = b2;
    }
    __syncthreads();
    float mean = red[16] * (1.f / CDIM);
    float var  = red[17] * (1.f / CDIM) - mean * mean;
    float inv  = rsqrtf(var + 1e-6f);
#pragma unroll
    for (int ci = 0; ci < 2; ci++) {
        int c = threadIdx.x + ci * 256;
        size_t oidx = ((size_t)b * NTOK + n) * CDIM + c;
        float v = ob[oidx] + (vals[c] - mean) * inv * g[c] + beta[c];
        __half hb = __float2half(v);
        yh[oidx] = hb;
        yl[oidx] = __float2half(v - __half2float(hb));
    }
}

// ---------------- launch ----------------
extern "C" void kernel_launch(void* const* d_in, const int* in_sizes, int n_in,
                              void* d_out, int out_size)
{
    const float* x      = (const float*)d_in[0];
    const float* Wq     = (const float*)d_in[1];
    const float* bq     = (const float*)d_in[2];
    const float* Wkv    = (const float*)d_in[3];
    const float* bkv    = (const float*)d_in[4];
    const float* srw    = (const float*)d_in[5];
    const float* srb    = (const float*)d_in[6];
    const float* srg    = (const float*)d_in[7];
    const float* srbeta = (const float*)d_in[8];
    const float* upg    = (const float*)d_in[9];
    const float* upbeta = (const float*)d_in[10];
    const float* Wp     = (const float*)d_in[11];
    const float* bp     = (const float*)d_in[12];
    float* out = (float*)d_out;

    float *kvb, *ob;
    __half *yh, *yl, *xrh, *xrl, *qh, *kvh, *wqt, *wkvt, *wpt;
    cudaGetSymbolAddress((void**)&kvb, g_kv);
    cudaGetSymbolAddress((void**)&ob,  g_o);
    cudaGetSymbolAddress((void**)&yh,  g_yh);
    cudaGetSymbolAddress((void**)&yl,  g_yl);
    cudaGetSymbolAddress((void**)&qh,  g_qh);
    cudaGetSymbolAddress((void**)&kvh, g_kvh);
    cudaGetSymbolAddress((void**)&xrh, g_xrh);
    cudaGetSymbolAddress((void**)&xrl, g_xrl);
    cudaGetSymbolAddress((void**)&wqt, g_wqt);
    cudaGetSymbolAddress((void**)&wkvt, g_wkvt);
    cudaGetSymbolAddress((void**)&wpt, g_wpt);

    cudaFuncSetAttribute(gemm2h_kernel, cudaFuncAttributeMaxDynamicSharedMemorySize, G2_SMEM);

    wsplit_all_kernel<<<1024, 256>>>(Wq, Wkv, Wp, wqt, wkvt, wpt);                 // 1
    conv_ln_kernel<<<BATCH * NSR, 256>>>(x, srw, srb, srg, srbeta, xrh, xrl);      // 2

    // kv = xr @ Wkv + bkv -> f32 (upsample) + fp16 (attention)
    gemm2h_kernel<<<dim3(1024 / 128, (BATCH * NSR + 127) / 128), 256, G2_SMEM>>>(  // 3
        xrh, xrl, wkvt, bkv, kvb, kvh, BATCH * NSR, 1024);
    // q = cvt16(x) @ Wq + bq -> fp16 (fused conversion)
    gemm1hf_kernel<<<dim3(512 / 128, (BATCH * NTOK) / 128), 256>>>(                // 4
        x, wqt, bq, qh, BATCH * NTOK, 512);

    attn_mma_kernel<<<dim3(NTOK / 64, BATCH * NHEADS), 128>>>(qh, kvh, ob);        // 5

    ups_ln_add_kernel<<<BATCH * NTOK, 256>>>(kvb, ob, upg, upbeta, yh, yl);        // 6

    // out = (yh+yl) @ Wp + bp -> f32 (2-term fp16)
    gemm2h_kernel<<<dim3(512 / 128, (BATCH * NTOK) / 128), 256, G2_SMEM>>>(        // 7
        yh, yl, wpt, bp, out, (__half*)nullptr, BATCH * NTOK, 512);
}

// round 16
// speedup vs baseline: 1.1455x; 1.0131x over previous
#include <cuda_runtime.h>
#include <cuda_bf16.h>
#include <cuda_fp16.h>
#include <math.h>
#include <float.h>
#include <stdint.h>

#define BATCH 2
#define NTOK  8000
#define CDIM  512
#define NSR   1000
#define NHEADS 8
#define HD    64

__device__ float g_kv[BATCH * NSR * 2 * CDIM];
__device__ __half g_oh [BATCH * NTOK * CDIM];
__device__ __half g_xh [BATCH * NTOK * CDIM];
__device__ __half g_yh [BATCH * NTOK * CDIM];
__device__ __half g_yl [BATCH * NTOK * CDIM];
__device__ __half g_qh [BATCH * NTOK * CDIM];
__device__ __half g_kvh[BATCH * NSR * 2 * CDIM];
__device__ __half g_xrh[BATCH * NSR * CDIM];
__device__ __half g_xrl[BATCH * NSR * CDIM];
__device__ __half g_wqt [CDIM * CDIM];
__device__ __half g_wkvt[2 * CDIM * CDIM];
__device__ __half g_wpt [CDIM * CDIM];

// ---------------- ptx helpers ----------------
__device__ __forceinline__ void ldsm4(uint32_t& r0, uint32_t& r1, uint32_t& r2, uint32_t& r3,
                                      uint32_t addr)
{
    asm volatile("ldmatrix.sync.aligned.m8n8.x4.shared.b16 {%0,%1,%2,%3}, [%4];"
                 : "=r"(r0), "=r"(r1), "=r"(r2), "=r"(r3) : "r"(addr));
}
__device__ __forceinline__ void ldsm4t(uint32_t& r0, uint32_t& r1, uint32_t& r2, uint32_t& r3,
                                       uint32_t addr)
{
    asm volatile("ldmatrix.sync.aligned.m8n8.x4.trans.shared.b16 {%0,%1,%2,%3}, [%4];"
                 : "=r"(r0), "=r"(r1), "=r"(r2), "=r"(r3) : "r"(addr));
}
__device__ __forceinline__ void mma16816h(float* c, const uint32_t* a, const uint32_t* b)
{
    asm volatile("mma.sync.aligned.m16n8k16.row.col.f32.f16.f16.f32 "
                 "{%0,%1,%2,%3}, {%4,%5,%6,%7}, {%8,%9}, {%0,%1,%2,%3};"
                 : "+f"(c[0]), "+f"(c[1]), "+f"(c[2]), "+f"(c[3])
                 : "r"(a[0]), "r"(a[1]), "r"(a[2]), "r"(a[3]), "r"(b[0]), "r"(b[1]));
}
__device__ __forceinline__ uint32_t packh2(float a, float b) {
    __half2 t = __floats2half2_rn(a, b);
    return *(uint32_t*)&t;
}
__device__ __forceinline__ void cpa16(uint32_t dst, const void* src) {
    asm volatile("cp.async.cg.shared.global [%0], [%1], 16;" :: "r"(dst), "l"(src) : "memory");
}
__device__ __forceinline__ void cpa16z(uint32_t dst, const void* src, int sz) {
    asm volatile("cp.async.cg.shared.global [%0], [%1], 16, %2;"
                 :: "r"(dst), "l"(src), "r"(sz) : "memory");
}
#define CPA_COMMIT() asm volatile("cp.async.commit_group;" ::: "memory")
#define CPA_WAIT1()  asm volatile("cp.async.wait_group 1;" ::: "memory")
#define CPA_WAIT0()  asm volatile("cp.async.wait_group 0;" ::: "memory")

// ---------------- convert fp32 -> fp16 ----------------
__global__ void __launch_bounds__(256) cvt_kernel(
    const float* __restrict__ s, __half* __restrict__ h, int n)
{
    int i = (blockIdx.x * 256 + threadIdx.x) * 4;
    if (i < n) {
        float4 f = *(const float4*)&s[i];
        __half2 a = __floats2half2_rn(f.x, f.y);
        __half2 b = __floats2half2_rn(f.z, f.w);
        uint2 pk; pk.x = *(uint32_t*)&a; pk.y = *(uint32_t*)&b;
        *(uint2*)&h[i] = pk;
    }
}

// ---------------- transpose ALL weights to fp16 [N][K] in one launch ----------------
__global__ void __launch_bounds__(256) wsplit_all_kernel(
    const float* __restrict__ Wq, const float* __restrict__ Wkv,
    const float* __restrict__ Wp,
    __half* __restrict__ qt, __half* __restrict__ kt, __half* __restrict__ pt)
{
    __shared__ float t[32][33];
    int tb = blockIdx.x;
    const float* W; __half* T; int N, nb, kb;
    if (tb < 256)      { W = Wq;  T = qt; N = 512;  int tt = tb;       nb = (tt & 15) * 32; kb = (tt >> 4) * 32; }
    else if (tb < 768) { W = Wkv; T = kt; N = 1024; int tt = tb - 256; nb = (tt & 31) * 32; kb = (tt >> 5) * 32; }
    else               { W = Wp;  T = pt; N = 512;  int tt = tb - 768; nb = (tt & 15) * 32; kb = (tt >> 4) * 32; }
    const int K = 512;
    int tx = threadIdx.x & 31, ty = threadIdx.x >> 5;
#pragma unroll
    for (int i = ty; i < 32; i += 8)
        t[i][tx] = W[(size_t)(kb + i) * N + nb + tx];
    __syncthreads();
#pragma unroll
    for (int i = ty; i < 32; i += 8)
        T[(size_t)(nb + i) * K + kb + tx] = __float2half(t[tx][i]);
}

// ---------------- conv3d depthwise (3,s2,p1) + bias + LN -> fp16 hi/lo ----------------
__global__ void __launch_bounds__(256) conv_ln_kernel(
    const float* __restrict__ x, const float* __restrict__ srw,
    const float* __restrict__ srb, const float* __restrict__ g,
    const float* __restrict__ beta,
    __half* __restrict__ xrh, __half* __restrict__ xrl)
{
    int bp = blockIdx.x;
    int b = bp / NSR, opos = bp % NSR;
    int od = opos / 100, oh = (opos / 10) % 10, ow = opos % 10;
    __shared__ float vals[CDIM];
    __shared__ float red[18];
    float loc[2];
#pragma unroll
    for (int ci = 0; ci < 2; ci++) {
        int c = threadIdx.x + ci * 256;
        float acc = srb[c];
#pragma unroll
        for (int kd = 0; kd < 3; kd++) {
            int id = od * 2 - 1 + kd;
            if ((unsigned)id >= 20u) continue;
#pragma unroll
            for (int kh = 0; kh < 3; kh++) {
                int ih = oh * 2 - 1 + kh;
                if ((unsigned)ih >= 20u) continue;
#pragma unroll
                for (int kw = 0; kw < 3; kw++) {
                    int iw = ow * 2 - 1 + kw;
                    if ((unsigned)iw >= 20u) continue;
                    acc += x[((size_t)b * NTOK + id * 400 + ih * 20 + iw) * CDIM + c] *
                           srw[c * 27 + kd * 9 + kh * 3 + kw];
                }
            }
        }
        vals[c] = acc; loc[ci] = acc;
    }
    float s = loc[0] + loc[1], sq = loc[0] * loc[0] + loc[1] * loc[1];
#pragma unroll
    for (int o2 = 16; o2 > 0; o2 >>= 1) {
        s  += __shfl_down_sync(0xffffffffu, s,  o2);
        sq += __shfl_down_sync(0xffffffffu, sq, o2);
    }
    int w = threadIdx.x >> 5;
    if ((threadIdx.x & 31) == 0) { red[w] = s; red[8 + w] = sq; }
    __syncthreads();
    if (threadIdx.x == 0) {
        float a = 0.f, b2 = 0.f;
        for (int i = 0; i < 8; i++) { a += red[i]; b2 += red[8 + i]; }
        red[16] = a; red[17] = b2;
    }
    __syncthreads();
    float mean = red[16] * (1.f / CDIM);
    float var  = red[17] * (1.f / CDIM) - mean * mean;
    float inv  = rsqrtf(var + 1e-6f);
#pragma unroll
    for (int ci = 0; ci < 2; ci++) {
        int c = threadIdx.x + ci * 256;
        float v = (vals[c] - mean) * inv * g[c] + beta[c];
        size_t idx = ((size_t)b * NSR + opos) * CDIM + c;
        __half hh = __float2half(v);
        xrh[idx] = hh;
        xrl[idx] = __float2half(v - __half2float(hh));
    }
}

#define SMS 72   // row stride for BK=64 tiles (144B: ldmatrix conflict-free)
#define GT_BYTES (128 * SMS * 2)        // 18432 B per 128x64 fp16 tile
#define G2_STAGE (3 * GT_BYTES)
#define G2_SMEM  (2 * G2_STAGE)         // 110592 B
#define G1_STAGE (2 * GT_BYTES)
#define G1_SMEM  (2 * G1_STAGE)         // 73728 B

// ---------------- fp16 2-term GEMM (BK=64, cp.async double-buffered) ----------------
__global__ void __launch_bounds__(256, 2) gemm2h_kernel(
    const __half* __restrict__ Ah, const __half* __restrict__ Al,
    const __half* __restrict__ B, const float* __restrict__ bias,
    float* __restrict__ C, __half* __restrict__ Ch, int M, int N)
{
    extern __shared__ __align__(16) __half g2sm[];
    uint32_t sbase = (uint32_t)__cvta_generic_to_shared(g2sm);

    int tid = threadIdx.x, wid = tid >> 5, lane = tid & 31;
    int wr = wid >> 2, wc = wid & 3;
    int rowBase = blockIdx.y * 128, colBase = blockIdx.x * 128;

    float acc[4][4][4];
#pragma unroll
    for (int i = 0; i < 4; i++)
#pragma unroll
        for (int j = 0; j < 4; j++)
#pragma unroll
            for (int k = 0; k < 4; k++) acc[i][j][k] = 0.f;

#define G2_LOAD(st, k0) do { \
        uint32_t stb = sbase + (uint32_t)((st) * G2_STAGE); \
        _Pragma("unroll") \
        for (int it = 0; it < 4; it++) { \
            int idx = tid + it * 256; \
            int r = idx >> 3, c = idx & 7; \
            int ar = rowBase + r; if (ar > M - 1) ar = M - 1; \
            int br = colBase + r; \
            size_t aoff = (size_t)ar * 512 + (k0) + c * 8; \
            size_t boff = (size_t)br * 512 + (k0) + c * 8; \
            uint32_t so = (uint32_t)((r * SMS + c * 8) * 2); \
            cpa16(stb + so,                Ah + aoff); \
            cpa16(stb + GT_BYTES + so,     Al + aoff); \
            cpa16(stb + 2 * GT_BYTES + so, B  + boff); \
        } \
    } while (0)

    G2_LOAD(0, 0);
    CPA_COMMIT();

    for (int ck = 0; ck < 8; ck++) {
        if (ck + 1 < 8) { G2_LOAD((ck + 1) & 1, (ck + 1) * 64); CPA_COMMIT(); CPA_WAIT1(); }
        else            { CPA_WAIT0(); }
        __syncthreads();

        uint32_t stb = sbase + (uint32_t)((ck & 1) * G2_STAGE);
        uint32_t aBaseH = stb, aBaseL = stb + GT_BYTES, bBase = stb + 2 * GT_BYTES;

#pragma unroll
        for (int ks = 0; ks < 64; ks += 16) {
            uint32_t aoffs = (uint32_t)(((wr * 64 + (lane & 15)) * SMS + ks + ((lane >> 4) << 3)) * 2);
            uint32_t boffs = (uint32_t)(((wc * 32 + ((lane >> 4) << 3) + (lane & 7)) * SMS + ks + (((lane >> 3) & 1) << 3)) * 2);

            uint32_t ah[4][4], al[4][4];
#pragma unroll
            for (int mf = 0; mf < 4; mf++) {
                uint32_t ao = aoffs + (uint32_t)(mf * 16 * SMS * 2);
                ldsm4(ah[mf][0], ah[mf][1], ah[mf][2], ah[mf][3], aBaseH + ao);
                ldsm4(al[mf][0], al[mf][1], al[mf][2], al[mf][3], aBaseL + ao);
            }
            uint32_t bh[4][2];
#pragma unroll
            for (int np = 0; np < 2; np++) {
                uint32_t bo = boffs + (uint32_t)(np * 16 * SMS * 2);
                ldsm4(bh[np * 2][0], bh[np * 2][1], bh[np * 2 + 1][0], bh[np * 2 + 1][1], bBase + bo);
            }
#pragma unroll
            for (int mf = 0; mf < 4; mf++)
#pragma unroll
                for (int nf = 0; nf < 4; nf++) {
                    mma16816h(acc[mf][nf], ah[mf], bh[nf]);
                    mma16816h(acc[mf][nf], al[mf], bh[nf]);
                }
        }
        __syncthreads();
    }
#undef G2_LOAD

#pragma unroll
    for (int mf = 0; mf < 4; mf++) {
#pragma unroll
        for (int nf = 0; nf < 4; nf++) {
            int row0 = rowBase + wr * 64 + mf * 16 + (lane >> 2);
            int col  = colBase + wc * 32 + nf * 8 + 2 * (lane & 3);
            float b0 = bias[col], b1 = bias[col + 1];
#pragma unroll
            for (int half = 0; half < 2; half++) {
                int row = row0 + half * 8;
                if (row < M) {
                    float v0 = acc[mf][nf][half * 2]     + b0;
                    float v1 = acc[mf][nf][half * 2 + 1] + b1;
                    size_t o0 = (size_t)row * N + col;
                    if (C) { C[o0] = v0; C[o0 + 1] = v1; }
                    if (Ch) {
                        Ch[o0]     = __float2half(v0);
                        Ch[o0 + 1] = __float2half(v1);
                    }
                }
            }
        }
    }
}

// ---------------- fp16 1-term GEMM (BK=64, cp.async double-buffered) ----------------
__global__ void __launch_bounds__(256, 2) gemm1h_kernel(
    const __half* __restrict__ A, const __half* __restrict__ B,
    const float* __restrict__ bias, __half* __restrict__ Ch, int M, int N)
{
    extern __shared__ __align__(16) __half g1sm[];
    uint32_t sbase = (uint32_t)__cvta_generic_to_shared(g1sm);

    int tid = threadIdx.x, wid = tid >> 5, lane = tid & 31;
    int wr = wid >> 2, wc = wid & 3;
    int rowBase = blockIdx.y * 128, colBase = blockIdx.x * 128;

    float acc[4][4][4];
#pragma unroll
    for (int i = 0; i < 4; i++)
#pragma unroll
        for (int j = 0; j < 4; j++)
#pragma unroll
            for (int k = 0; k < 4; k++) acc[i][j][k] = 0.f;

#define G1_LOAD(st, k0) do { \
        uint32_t stb = sbase + (uint32_t)((st) * G1_STAGE); \
        _Pragma("unroll") \
        for (int it = 0; it < 4; it++) { \
            int idx = tid + it * 256; \
            int r = idx >> 3, c = idx & 7; \
            int ar = rowBase + r; if (ar > M - 1) ar = M - 1; \
            int br = colBase + r; \
            size_t aoff = (size_t)ar * 512 + (k0) + c * 8; \
            size_t boff = (size_t)br * 512 + (k0) + c * 8; \
            uint32_t so = (uint32_t)((r * SMS + c * 8) * 2); \
            cpa16(stb + so,            A + aoff); \
            cpa16(stb + GT_BYTES + so, B + boff); \
        } \
    } while (0)

    G1_LOAD(0, 0);
    CPA_COMMIT();

    for (int ck = 0; ck < 8; ck++) {
        if (ck + 1 < 8) { G1_LOAD((ck + 1) & 1, (ck + 1) * 64); CPA_COMMIT(); CPA_WAIT1(); }
        else            { CPA_WAIT0(); }
        __syncthreads();

        uint32_t stb = sbase + (uint32_t)((ck & 1) * G1_STAGE);
        uint32_t aBase = stb, bBase = stb + GT_BYTES;

#pragma unroll
        for (int ks = 0; ks < 64; ks += 16) {
            uint32_t aoffs = (uint32_t)(((wr * 64 + (lane & 15)) * SMS + ks + ((lane >> 4) << 3)) * 2);
            uint32_t boffs = (uint32_t)(((wc * 32 + ((lane >> 4) << 3) + (lane & 7)) * SMS + ks + (((lane >> 3) & 1) << 3)) * 2);

            uint32_t a_[4][4];
#pragma unroll
            for (int mf = 0; mf < 4; mf++) {
                uint32_t ao = aoffs + (uint32_t)(mf * 16 * SMS * 2);
                ldsm4(a_[mf][0], a_[mf][1], a_[mf][2], a_[mf][3], aBase + ao);
            }
            uint32_t bh[4][2];
#pragma unroll
            for (int np = 0; np < 2; np++) {
                uint32_t bo = boffs + (uint32_t)(np * 16 * SMS * 2);
                ldsm4(bh[np * 2][0], bh[np * 2][1], bh[np * 2 + 1][0], bh[np * 2 + 1][1], bBase + bo);
            }
#pragma unroll
            for (int mf = 0; mf < 4; mf++)
#pragma unroll
                for (int nf = 0; nf < 4; nf++)
                    mma16816h(acc[mf][nf], a_[mf], bh[nf]);
        }
        __syncthreads();
    }
#undef G1_LOAD

#pragma unroll
    for (int mf = 0; mf < 4; mf++) {
#pragma unroll
        for (int nf = 0; nf < 4; nf++) {
            int row0 = rowBase + wr * 64 + mf * 16 + (lane >> 2);
            int col  = colBase + wc * 32 + nf * 8 + 2 * (lane & 3);
            float b0 = bias[col], b1 = bias[col + 1];
#pragma unroll
            for (int half = 0; half < 2; half++) {
                int row = row0 + half * 8;
                if (row < M) {
                    size_t o0 = (size_t)row * N + col;
                    Ch[o0]     = __float2half(acc[mf][nf][half * 2]     + b0);
                    Ch[o0 + 1] = __float2half(acc[mf][nf][half * 2 + 1] + b1);
                }
            }
        }
    }
}

// ---------------- flash attention: 64-q tile, cp.async DB KV, fp16 output ----------------
#define AST 72
#define AT_TILE_BYTES (64 * AST * 2)
#define AT_SCALE 0.18033688f            // 0.125 * log2(e)
__global__ void __launch_bounds__(128) attn_mma_kernel(
    const __half* __restrict__ q, const __half* __restrict__ kvh,
    __half* __restrict__ o)
{
    __shared__ __half sQ[64 * AST];
    __shared__ __half sKV[4 * 64 * AST];

    int tid = threadIdx.x, wid = tid >> 5, lane = tid & 31;
    int bh = blockIdx.y, b = bh >> 3, h = bh & 7;
    int qbase = blockIdx.x * 64;
    size_t qoff = ((size_t)b * NTOK + qbase) * CDIM + h * HD;

#pragma unroll
    for (int i = 0; i < 4; i++) {
        int idx = tid + i * 128;
        int r = idx >> 3, c = (idx & 7) << 3;
        *(uint4*)&sQ[r * AST + c] = *(const uint4*)&q[qoff + (size_t)r * CDIM + c];
    }
    __syncthreads();

    uint32_t bQ   = (uint32_t)__cvta_generic_to_shared(sQ);
    uint32_t kvBs = (uint32_t)__cvta_generic_to_shared(sKV);

    uint32_t qf[4][4];
    {
        uint32_t qrow = (uint32_t)(wid * 16 + (lane & 15));
#pragma unroll
        for (int kt = 0; kt < 4; kt++) {
            uint32_t off = (qrow * AST + kt * 16 + ((lane >> 4) << 3)) * 2;
            ldsm4(qf[kt][0], qf[kt][1], qf[kt][2], qf[kt][3], bQ + off);
        }
    }

    float acc[8][4];
#pragma unroll
    for (int i = 0; i < 8; i++)
#pragma unroll
        for (int j = 0; j < 4; j++) acc[i][j] = 0.f;
    float m0 = -FLT_MAX, m1 = -FLT_MAX, l0 = 0.f, l1 = 0.f;

    size_t kvoff = (size_t)b * NSR * 1024 + h * HD;
    int cbase = 2 * (lane & 3);

#define AT_LOAD(st, kb) do { \
        uint32_t stb = kvBs + (uint32_t)((st) * 2 * AT_TILE_BYTES); \
        _Pragma("unroll") \
        for (int i = 0; i < 4; i++) { \
            int idx = tid + i * 128; \
            int r = idx >> 3, c = (idx & 7) << 3; \
            int gm = (kb) + r; \
            int sz = (gm < NSR) ? 16 : 0; \
            int gmc = (gm < NSR) ? gm : (NSR - 1); \
            const __half* src = kvh + kvoff + (size_t)gmc * 1024 + c; \
            uint32_t so = (uint32_t)((r * AST + c) * 2); \
            cpa16z(stb + so,                 src,       sz); \
            cpa16z(stb + AT_TILE_BYTES + so, src + 512, sz); \
        } \
    } while (0)

    AT_LOAD(0, 0);
    CPA_COMMIT();

    for (int it = 0; it < 16; it++) {
        if (it + 1 < 16) { AT_LOAD((it + 1) & 1, (it + 1) * 64); CPA_COMMIT(); CPA_WAIT1(); }
        else             { CPA_WAIT0(); }
        __syncthreads();

        uint32_t stb = kvBs + (uint32_t)((it & 1) * 2 * AT_TILE_BYTES);
        uint32_t bK = stb, bV = stb + AT_TILE_BYTES;
        int kb = it * 64;

        float s_[8][4];
#pragma unroll
        for (int i = 0; i < 8; i++)
#pragma unroll
            for (int j = 0; j < 4; j++) s_[i][j] = 0.f;

#pragma unroll
        for (int kt = 0; kt < 4; kt++) {
#pragma unroll
            for (int np = 0; np < 4; np++) {
                uint32_t brow = (uint32_t)(np * 16 + ((lane >> 4) << 3) + (lane & 7));
                uint32_t boff = (brow * AST + kt * 16 + (((lane >> 3) & 1) << 3)) * 2;
                uint32_t h0, h1, h2, h3;
                ldsm4(h0, h1, h2, h3, bK + boff);
                uint32_t fh0[2] = {h0, h1}, fh1[2] = {h2, h3};
                mma16816h(s_[np * 2],     qf[kt], fh0);
                mma16816h(s_[np * 2 + 1], qf[kt], fh1);
            }
        }

        int valid = NSR - kb; if (valid > 64) valid = 64;
        float rm0 = -FLT_MAX, rm1 = -FLT_MAX;
#pragma unroll
        for (int nt = 0; nt < 8; nt++) {
#pragma unroll
            for (int j = 0; j < 4; j++) s_[nt][j] *= AT_SCALE;
            rm0 = fmaxf(rm0, fmaxf(s_[nt][0], s_[nt][1]));
            rm1 = fmaxf(rm1, fmaxf(s_[nt][2], s_[nt][3]));
        }
        rm0 = fmaxf(rm0, __shfl_xor_sync(0xffffffffu, rm0, 1));
        rm0 = fmaxf(rm0, __shfl_xor_sync(0xffffffffu, rm0, 2));
        rm1 = fmaxf(rm1, __shfl_xor_sync(0xffffffffu, rm1, 1));
        rm1 = fmaxf(rm1, __shfl_xor_sync(0xffffffffu, rm1, 2));
        float nm0 = fmaxf(m0, rm0), nm1 = fmaxf(m1, rm1);
        float corr0 = exp2f(m0 - nm0), corr1 = exp2f(m1 - nm1);
        m0 = nm0; m1 = nm1;

        float sum0 = 0.f, sum1 = 0.f;
#pragma unroll
        for (int nt = 0; nt < 8; nt++) {
            int c0 = nt * 8 + cbase;
            float p0 = (c0     < valid) ? exp2f(s_[nt][0] - nm0) : 0.f;
            float p1 = (c0 + 1 < valid) ? exp2f(s_[nt][1] - nm0) : 0.f;
            float p2 = (c0     < valid) ? exp2f(s_[nt][2] - nm1) : 0.f;
            float p3 = (c0 + 1 < valid) ? exp2f(s_[nt][3] - nm1) : 0.f;
            sum0 += p0 + p1; sum1 += p2 + p3;
            s_[nt][0] = p0; s_[nt][1] = p1; s_[nt][2] = p2; s_[nt][3] = p3;
        }
        sum0 += __shfl_xor_sync(0xffffffffu, sum0, 1);
        sum0 += __shfl_xor_sync(0xffffffffu, sum0, 2);
        sum1 += __shfl_xor_sync(0xffffffffu, sum1, 1);
        sum1 += __shfl_xor_sync(0xffffffffu, sum1, 2);
        l0 = l0 * corr0 + sum0;
        l1 = l1 * corr1 + sum1;

#pragma unroll
        for (int nt = 0; nt < 8; nt++) {
            acc[nt][0] *= corr0; acc[nt][1] *= corr0;
            acc[nt][2] *= corr1; acc[nt][3] *= corr1;
        }

#pragma unroll
        for (int kt = 0; kt < 4; kt++) {
            uint32_t ph[4];
#pragma unroll
            for (int q2 = 0; q2 < 2; q2++) {
                int nt = 2 * kt + q2;
                ph[q2 * 2]     = packh2(s_[nt][0], s_[nt][1]);
                ph[q2 * 2 + 1] = packh2(s_[nt][2], s_[nt][3]);
            }
            int l8 = lane >> 3, li = lane & 7;
#pragma unroll
            for (int np = 0; np < 4; np++) {
                uint32_t vrow = (uint32_t)(kt * 16 + ((l8 & 1) << 3) + li);
                uint32_t vcol = (uint32_t)(np * 16 + ((l8 >> 1) << 3));
                uint32_t voff = (vrow * AST + vcol) * 2;
                uint32_t h0, h1, h2, h3;
                ldsm4t(h0, h1, h2, h3, bV + voff);
                uint32_t fh0[2] = {h0, h1}, fh1[2] = {h2, h3};
                mma16816h(acc[np * 2],     ph, fh0);
                mma16816h(acc[np * 2 + 1], ph, fh1);
            }
        }
        __syncthreads();
    }
#undef AT_LOAD

    float inv0 = 1.f / l0, inv1 = 1.f / l1;
    int r0 = qbase + wid * 16 + (lane >> 2);
    size_t ob0 = ((size_t)b * NTOK + r0) * CDIM + h * HD;
    size_t ob1 = ob0 + (size_t)8 * CDIM;
#pragma unroll
    for (int nt = 0; nt < 8; nt++) {
        int cc = nt * 8 + cbase;
        *(uint32_t*)&o[ob0 + cc] = packh2(acc[nt][0] * inv0, acc[nt][1] * inv0);
        *(uint32_t*)&o[ob1 + cc] = packh2(acc[nt][2] * inv1, acc[nt][3] * inv1);
    }
}

// ---------------- trilinear upsample of V + LN + add o(fp16) -> fp16 hi/lo ----------------
__global__ void __launch_bounds__(256) ups_ln_add_kernel(
    const float* __restrict__ kv, const __half* __restrict__ ob,
    const float* __restrict__ g, const float* __restrict__ beta,
    __half* __restrict__ yh, __half* __restrict__ yl)
{
    int bn = blockIdx.x;
    int b = bn / NTOK, n = bn % NTOK;
    int d = n / 400, hh = (n / 20) % 20, ww = n % 20;
    float sd = d  * 0.5f - 0.25f; int fd = (int)floorf(sd); float wdz = sd - (float)fd;
    float sh = hh * 0.5f - 0.25f; int fh = (int)floorf(sh); float why = sh - (float)fh;
    float sw = ww * 0.5f - 0.25f; int fw = (int)floorf(sw); float wwx = sw - (float)fw;
    int dz0 = fd < 0 ? 0 : fd; int dz1 = (fd + 1) > 9 ? 9 : (fd + 1);
    int hy0 = fh < 0 ? 0 : fh; int hy1 = (fh + 1) > 9 ? 9 : (fh + 1);
    int wx0 = fw < 0 ? 0 : fw; int wx1 = (fw + 1) > 9 ? 9 : (fw + 1);
    int midx[8]; float wt8[8];
    {
        int zz[2] = {dz0, dz1};  float wz[2] = {1.f - wdz, wdz};
        int yy[2] = {hy0, hy1};  float wy[2] = {1.f - why, why};
        int xx[2] = {wx0, wx1};  float wx[2] = {1.f - wwx, wwx};
        int t = 0;
        for (int a = 0; a < 2; a++)
            for (int b2 = 0; b2 < 2; b2++)
                for (int c2 = 0; c2 < 2; c2++) {
                    midx[t] = zz[a] * 100 + yy[b2] * 10 + xx[c2];
                    wt8[t]  = wz[a] * wy[b2] * wx[c2]; t++;
                }
    }
    __shared__ float vals[CDIM];
    __shared__ float red[18];
    size_t kvb = (size_t)b * NSR * 1024 + 512;
    float loc[2];
#pragma unroll
    for (int ci = 0; ci < 2; ci++) {
        int c = threadIdx.x + ci * 256;
        float acc = 0.f;
#pragma unroll
        for (int t = 0; t < 8; t++)
            acc += wt8[t] * kv[kvb + (size_t)midx[t] * 1024 + c];
        vals[c] = acc; loc[ci] = acc;
    }
    float s = loc[0] + loc[1], sq = loc[0] * loc[0] + loc[1] * loc[1];
#pragma unroll
    for (int o2 = 16; o2 > 0; o2 >>= 1) {
        s  += __shfl_down_sync(0xffffffffu, s,  o2);
        sq += __shfl_down_sync(0xffffffffu, sq, o2);
    }
    int w = threadIdx.x >> 5;
    if ((threadIdx.x & 31) == 0) { red[w] = s; red[8 + w] = sq; }
    __syncthreads();
    if (threadIdx.x == 0) {
        float a = 0.f, b2 = 0.f;
        for (int i = 0; i < 8; i++) { a += red[i]; b2 += red[8 + i]; }
        red[16] = a; red[17] = b2;
    }
    __syncthreads();
    float mean = red[16] * (1.f / CDIM);
    float var  = red[17] * (1.f / CDIM) - mean * mean;
    float inv  = rsqrtf(var + 1e-6f);
#pragma unroll
    for (int ci = 0; ci < 2; ci++) {
        int c = threadIdx.x + ci * 256;
        size_t oidx = ((size_t)b * NTOK + n) * CDIM + c;
        float v = __half2float(ob[oidx]) + (vals[c] - mean) * inv * g[c] + beta[c];
        __half hb = __float2half(v);
        yh[oidx] = hb;
        yl[oidx] = __float2half(v - __half2float(hb));
    }
}

// ---------------- launch ----------------
extern "C" void kernel_launch(void* const* d_in, const int* in_sizes, int n_in,
                              void* d_out, int out_size)
{
    const float* x      = (const float*)d_in[0];
    const float* Wq     = (const float*)d_in[1];
    const float* bq     = (const float*)d_in[2];
    const float* Wkv    = (const float*)d_in[3];
    const float* bkv    = (const float*)d_in[4];
    const float* srw    = (const float*)d_in[5];
    const float* srb    = (const float*)d_in[6];
    const float* srg    = (const float*)d_in[7];
    const float* srbeta = (const float*)d_in[8];
    const float* upg    = (const float*)d_in[9];
    const float* upbeta = (const float*)d_in[10];
    const float* Wp     = (const float*)d_in[11];
    const float* bp     = (const float*)d_in[12];
    float* out = (float*)d_out;

    float* kvb;
    __half *oh, *xh, *yh, *yl, *xrh, *xrl, *qh, *kvh, *wqt, *wkvt, *wpt;
    cudaGetSymbolAddress((void**)&kvb, g_kv);
    cudaGetSymbolAddress((void**)&oh,  g_oh);
    cudaGetSymbolAddress((void**)&xh,  g_xh);
    cudaGetSymbolAddress((void**)&yh,  g_yh);
    cudaGetSymbolAddress((void**)&yl,  g_yl);
    cudaGetSymbolAddress((void**)&qh,  g_qh);
    cudaGetSymbolAddress((void**)&kvh, g_kvh);
    cudaGetSymbolAddress((void**)&xrh, g_xrh);
    cudaGetSymbolAddress((void**)&xrl, g_xrl);
    cudaGetSymbolAddress((void**)&wqt, g_wqt);
    cudaGetSymbolAddress((void**)&wkvt, g_wkvt);
    cudaGetSymbolAddress((void**)&wpt, g_wpt);

    cudaFuncSetAttribute(gemm2h_kernel, cudaFuncAttributeMaxDynamicSharedMemorySize, G2_SMEM);
    cudaFuncSetAttribute(gemm1h_kernel, cudaFuncAttributeMaxDynamicSharedMemorySize, G1_SMEM);

    int nx = BATCH * NTOK * CDIM;
    wsplit_all_kernel<<<1024, 256>>>(Wq, Wkv, Wp, wqt, wkvt, wpt);                 // 1
    cvt_kernel<<<(nx / 4 + 255) / 256, 256>>>(x, xh, nx);                          // 2
    conv_ln_kernel<<<BATCH * NSR, 256>>>(x, srw, srb, srg, srbeta, xrh, xrl);      // 3

    // kv = xr @ Wkv + bkv -> f32 (upsample) + fp16 (attention)
    gemm2h_kernel<<<dim3(1024 / 128, (BATCH * NSR + 127) / 128), 256, G2_SMEM>>>(  // 4
        xrh, xrl, wkvt, bkv, kvb, kvh, BATCH * NSR, 1024);
    // q = xh @ Wq + bq -> fp16 (cp.async DB)
    gemm1h_kernel<<<dim3(512 / 128, (BATCH * NTOK) / 128), 256, G1_SMEM>>>(        // 5
        xh, wqt, bq, qh, BATCH * NTOK, 512);

    attn_mma_kernel<<<dim3(NTOK / 64, BATCH * NHEADS), 128>>>(qh, kvh, oh);        // 6

    ups_ln_add_kernel<<<BATCH * NTOK, 256>>>(kvb, oh, upg, upbeta, yh, yl);        // 7

    // out = (yh+yl) @ Wp + bp -> f32 (2-term fp16)
    gemm2h_kernel<<<dim3(512 / 128, (BATCH * NTOK) / 128), 256, G2_SMEM>>>(        // 8
        yh, yl, wpt, bp, out, (__half*)nullptr, BATCH * NTOK, 512);
}

// round 17
// speedup vs baseline: 1.1579x; 1.0108x over previous
#include <cuda_runtime.h>
#include <cuda_bf16.h>
#include <cuda_fp16.h>
#include <math.h>
#include <float.h>
#include <stdint.h>

#define BATCH 2
#define NTOK  8000
#define CDIM  512
#define NSR   1000
#define NHEADS 8
#define HD    64

__device__ __half g_oh [BATCH * NTOK * CDIM];
__device__ __half g_xh [BATCH * NTOK * CDIM];
__device__ __half g_yh [BATCH * NTOK * CDIM];
__device__ __half g_yl [BATCH * NTOK * CDIM];
__device__ __half g_qh [BATCH * NTOK * CDIM];
__device__ __half g_kvh[BATCH * NSR * 2 * CDIM];
__device__ __half g_xrh[BATCH * NSR * CDIM];
__device__ __half g_xrl[BATCH * NSR * CDIM];
__device__ __half g_wqt [CDIM * CDIM];
__device__ __half g_wkvt[2 * CDIM * CDIM];
__device__ __half g_wpt [CDIM * CDIM];

// ---------------- ptx helpers ----------------
__device__ __forceinline__ void ldsm4(uint32_t& r0, uint32_t& r1, uint32_t& r2, uint32_t& r3,
                                      uint32_t addr)
{
    asm volatile("ldmatrix.sync.aligned.m8n8.x4.shared.b16 {%0,%1,%2,%3}, [%4];"
                 : "=r"(r0), "=r"(r1), "=r"(r2), "=r"(r3) : "r"(addr));
}
__device__ __forceinline__ void ldsm4t(uint32_t& r0, uint32_t& r1, uint32_t& r2, uint32_t& r3,
                                       uint32_t addr)
{
    asm volatile("ldmatrix.sync.aligned.m8n8.x4.trans.shared.b16 {%0,%1,%2,%3}, [%4];"
                 : "=r"(r0), "=r"(r1), "=r"(r2), "=r"(r3) : "r"(addr));
}
__device__ __forceinline__ void mma16816h(float* c, const uint32_t* a, const uint32_t* b)
{
    asm volatile("mma.sync.aligned.m16n8k16.row.col.f32.f16.f16.f32 "
                 "{%0,%1,%2,%3}, {%4,%5,%6,%7}, {%8,%9}, {%0,%1,%2,%3};"
                 : "+f"(c[0]), "+f"(c[1]), "+f"(c[2]), "+f"(c[3])
                 : "r"(a[0]), "r"(a[1]), "r"(a[2]), "r"(a[3]), "r"(b[0]), "r"(b[1]));
}
__device__ __forceinline__ uint32_t packh2(float a, float b) {
    __half2 t = __floats2half2_rn(a, b);
    return *(uint32_t*)&t;
}
__device__ __forceinline__ void cpa16(uint32_t dst, const void* src) {
    asm volatile("cp.async.cg.shared.global [%0], [%1], 16;" :: "r"(dst), "l"(src) : "memory");
}
__device__ __forceinline__ void cpa16z(uint32_t dst, const void* src, int sz) {
    asm volatile("cp.async.cg.shared.global [%0], [%1], 16, %2;"
                 :: "r"(dst), "l"(src), "r"(sz) : "memory");
}
#define CPA_COMMIT() asm volatile("cp.async.commit_group;" ::: "memory")
#define CPA_WAIT1()  asm volatile("cp.async.wait_group 1;" ::: "memory")
#define CPA_WAIT0()  asm volatile("cp.async.wait_group 0;" ::: "memory")

// ---------------- merged pre-pass: wsplit (1024) + cvt (8000) + conv_ln (2000) ----------------
#define PRE_WSPLIT 1024
#define PRE_CVT    8000
#define PRE_CONV   (BATCH * NSR)
__global__ void __launch_bounds__(256) pre_kernel(
    const float* __restrict__ Wq, const float* __restrict__ Wkv,
    const float* __restrict__ Wp,
    __half* __restrict__ qt, __half* __restrict__ kt, __half* __restrict__ pt,
    const float* __restrict__ x, __half* __restrict__ xh,
    const float* __restrict__ srw, const float* __restrict__ srb,
    const float* __restrict__ g, const float* __restrict__ beta,
    __half* __restrict__ xrh, __half* __restrict__ xrl)
{
    __shared__ float t[32][33];
    __shared__ float vals[CDIM];
    __shared__ float red[18];
    int tb = blockIdx.x;

    if (tb < PRE_WSPLIT) {
        // ---- weight transpose ----
        const float* W; __half* T; int N, nb, kb;
        if (tb < 256)      { W = Wq;  T = qt; N = 512;  int tt = tb;       nb = (tt & 15) * 32; kb = (tt >> 4) * 32; }
        else if (tb < 768) { W = Wkv; T = kt; N = 1024; int tt = tb - 256; nb = (tt & 31) * 32; kb = (tt >> 5) * 32; }
        else               { W = Wp;  T = pt; N = 512;  int tt = tb - 768; nb = (tt & 15) * 32; kb = (tt >> 4) * 32; }
        const int K = 512;
        int tx = threadIdx.x & 31, ty = threadIdx.x >> 5;
#pragma unroll
        for (int i = ty; i < 32; i += 8)
            t[i][tx] = W[(size_t)(kb + i) * N + nb + tx];
        __syncthreads();
#pragma unroll
        for (int i = ty; i < 32; i += 8)
            T[(size_t)(nb + i) * K + kb + tx] = __float2half(t[tx][i]);
        return;
    }
    if (tb < PRE_WSPLIT + PRE_CVT) {
        // ---- x -> fp16 ----
        int i = ((tb - PRE_WSPLIT) * 256 + threadIdx.x) * 4;
        float4 f = *(const float4*)&x[i];
        __half2 a = __floats2half2_rn(f.x, f.y);
        __half2 b = __floats2half2_rn(f.z, f.w);
        uint2 pk; pk.x = *(uint32_t*)&a; pk.y = *(uint32_t*)&b;
        *(uint2*)&xh[i] = pk;
        return;
    }
    // ---- conv3d depthwise + bias + LN -> fp16 hi/lo ----
    int bp = tb - PRE_WSPLIT - PRE_CVT;
    int b = bp / NSR, opos = bp % NSR;
    int od = opos / 100, oh = (opos / 10) % 10, ow = opos % 10;
    float loc[2];
#pragma unroll
    for (int ci = 0; ci < 2; ci++) {
        int c = threadIdx.x + ci * 256;
        float acc = srb[c];
#pragma unroll
        for (int kd = 0; kd < 3; kd++) {
            int id = od * 2 - 1 + kd;
            if ((unsigned)id >= 20u) continue;
#pragma unroll
            for (int kh = 0; kh < 3; kh++) {
                int ih = oh * 2 - 1 + kh;
                if ((unsigned)ih >= 20u) continue;
#pragma unroll
                for (int kw = 0; kw < 3; kw++) {
                    int iw = ow * 2 - 1 + kw;
                    if ((unsigned)iw >= 20u) continue;
                    acc += x[((size_t)b * NTOK + id * 400 + ih * 20 + iw) * CDIM + c] *
                           srw[c * 27 + kd * 9 + kh * 3 + kw];
                }
            }
        }
        vals[c] = acc; loc[ci] = acc;
    }
    float s = loc[0] + loc[1], sq = loc[0] * loc[0] + loc[1] * loc[1];
#pragma unroll
    for (int o2 = 16; o2 > 0; o2 >>= 1) {
        s  += __shfl_down_sync(0xffffffffu, s,  o2);
        sq += __shfl_down_sync(0xffffffffu, sq, o2);
    }
    int w = threadIdx.x >> 5;
    if ((threadIdx.x & 31) == 0) { red[w] = s; red[8 + w] = sq; }
    __syncthreads();
    if (threadIdx.x == 0) {
        float a = 0.f, b2 = 0.f;
        for (int i = 0; i < 8; i++) { a += red[i]; b2 += red[8 + i]; }
        red[16] = a; red[17] = b2;
    }
    __syncthreads();
    float mean = red[16] * (1.f / CDIM);
    float var  = red[17] * (1.f / CDIM) - mean * mean;
    float inv  = rsqrtf(var + 1e-6f);
#pragma unroll
    for (int ci = 0; ci < 2; ci++) {
        int c = threadIdx.x + ci * 256;
        float v = (vals[c] - mean) * inv * g[c] + beta[c];
        size_t idx = ((size_t)b * NSR + opos) * CDIM + c;
        __half hh = __float2half(v);
        xrh[idx] = hh;
        xrl[idx] = __float2half(v - __half2float(hh));
    }
}

#define SMS 72   // row stride for BK=64 tiles (144B: ldmatrix conflict-free)
#define GT_BYTES (128 * SMS * 2)        // 18432 B per 128x64 fp16 tile
#define G2_STAGE (3 * GT_BYTES)
#define G2_SMEM  (2 * G2_STAGE)         // 110592 B
#define G1_STAGE (2 * GT_BYTES)
#define G1_SMEM  (2 * G1_STAGE)         // 73728 B

// ---------------- fp16 2-term GEMM (BK=64, cp.async double-buffered) ----------------
__global__ void __launch_bounds__(256, 2) gemm2h_kernel(
    const __half* __restrict__ Ah, const __half* __restrict__ Al,
    const __half* __restrict__ B, const float* __restrict__ bias,
    float* __restrict__ C, __half* __restrict__ Ch, int M, int N)
{
    extern __shared__ __align__(16) __half g2sm[];
    uint32_t sbase = (uint32_t)__cvta_generic_to_shared(g2sm);

    int tid = threadIdx.x, wid = tid >> 5, lane = tid & 31;
    int wr = wid >> 2, wc = wid & 3;
    int rowBase = blockIdx.y * 128, colBase = blockIdx.x * 128;

    float acc[4][4][4];
#pragma unroll
    for (int i = 0; i < 4; i++)
#pragma unroll
        for (int j = 0; j < 4; j++)
#pragma unroll
            for (int k = 0; k < 4; k++) acc[i][j][k] = 0.f;

#define G2_LOAD(st, k0) do { \
        uint32_t stb = sbase + (uint32_t)((st) * G2_STAGE); \
        _Pragma("unroll") \
        for (int it = 0; it < 4; it++) { \
            int idx = tid + it * 256; \
            int r = idx >> 3, c = idx & 7; \
            int ar = rowBase + r; if (ar > M - 1) ar = M - 1; \
            int br = colBase + r; \
            size_t aoff = (size_t)ar * 512 + (k0) + c * 8; \
            size_t boff = (size_t)br * 512 + (k0) + c * 8; \
            uint32_t so = (uint32_t)((r * SMS + c * 8) * 2); \
            cpa16(stb + so,                Ah + aoff); \
            cpa16(stb + GT_BYTES + so,     Al + aoff); \
            cpa16(stb + 2 * GT_BYTES + so, B  + boff); \
        } \
    } while (0)

    G2_LOAD(0, 0);
    CPA_COMMIT();

    for (int ck = 0; ck < 8; ck++) {
        if (ck + 1 < 8) { G2_LOAD((ck + 1) & 1, (ck + 1) * 64); CPA_COMMIT(); CPA_WAIT1(); }
        else            { CPA_WAIT0(); }
        __syncthreads();

        uint32_t stb = sbase + (uint32_t)((ck & 1) * G2_STAGE);
        uint32_t aBaseH = stb, aBaseL = stb + GT_BYTES, bBase = stb + 2 * GT_BYTES;

#pragma unroll
        for (int ks = 0; ks < 64; ks += 16) {
            uint32_t aoffs = (uint32_t)(((wr * 64 + (lane & 15)) * SMS + ks + ((lane >> 4) << 3)) * 2);
            uint32_t boffs = (uint32_t)(((wc * 32 + ((lane >> 4) << 3) + (lane & 7)) * SMS + ks + (((lane >> 3) & 1) << 3)) * 2);

            uint32_t ah[4][4], al[4][4];
#pragma unroll
            for (int mf = 0; mf < 4; mf++) {
                uint32_t ao = aoffs + (uint32_t)(mf * 16 * SMS * 2);
                ldsm4(ah[mf][0], ah[mf][1], ah[mf][2], ah[mf][3], aBaseH + ao);
                ldsm4(al[mf][0], al[mf][1], al[mf][2], al[mf][3], aBaseL + ao);
            }
            uint32_t bh[4][2];
#pragma unroll
            for (int np = 0; np < 2; np++) {
                uint32_t bo = boffs + (uint32_t)(np * 16 * SMS * 2);
                ldsm4(bh[np * 2][0], bh[np * 2][1], bh[np * 2 + 1][0], bh[np * 2 + 1][1], bBase + bo);
            }
#pragma unroll
            for (int mf = 0; mf < 4; mf++)
#pragma unroll
                for (int nf = 0; nf < 4; nf++) {
                    mma16816h(acc[mf][nf], ah[mf], bh[nf]);
                    mma16816h(acc[mf][nf], al[mf], bh[nf]);
                }
        }
        __syncthreads();
    }
#undef G2_LOAD

#pragma unroll
    for (int mf = 0; mf < 4; mf++) {
#pragma unroll
        for (int nf = 0; nf < 4; nf++) {
            int row0 = rowBase + wr * 64 + mf * 16 + (lane >> 2);
            int col  = colBase + wc * 32 + nf * 8 + 2 * (lane & 3);
            float b0 = bias[col], b1 = bias[col + 1];
#pragma unroll
            for (int half = 0; half < 2; half++) {
                int row = row0 + half * 8;
                if (row < M) {
                    float v0 = acc[mf][nf][half * 2]     + b0;
                    float v1 = acc[mf][nf][half * 2 + 1] + b1;
                    size_t o0 = (size_t)row * N + col;
                    if (C) { C[o0] = v0; C[o0 + 1] = v1; }
                    if (Ch) {
                        Ch[o0]     = __float2half(v0);
                        Ch[o0 + 1] = __float2half(v1);
                    }
                }
            }
        }
    }
}

// ---------------- fp16 1-term GEMM (BK=64, cp.async double-buffered) ----------------
__global__ void __launch_bounds__(256, 2) gemm1h_kernel(
    const __half* __restrict__ A, const __half* __restrict__ B,
    const float* __restrict__ bias, __half* __restrict__ Ch, int M, int N)
{
    extern __shared__ __align__(16) __half g1sm[];
    uint32_t sbase = (uint32_t)__cvta_generic_to_shared(g1sm);

    int tid = threadIdx.x, wid = tid >> 5, lane = tid & 31;
    int wr = wid >> 2, wc = wid & 3;
    int rowBase = blockIdx.y * 128, colBase = blockIdx.x * 128;

    float acc[4][4][4];
#pragma unroll
    for (int i = 0; i < 4; i++)
#pragma unroll
        for (int j = 0; j < 4; j++)
#pragma unroll
            for (int k = 0; k < 4; k++) acc[i][j][k] = 0.f;

#define G1_LOAD(st, k0) do { \
        uint32_t stb = sbase + (uint32_t)((st) * G1_STAGE); \
        _Pragma("unroll") \
        for (int it = 0; it < 4; it++) { \
            int idx = tid + it * 256; \
            int r = idx >> 3, c = idx & 7; \
            int ar = rowBase + r; if (ar > M - 1) ar = M - 1; \
            int br = colBase + r; \
            size_t aoff = (size_t)ar * 512 + (k0) + c * 8; \
            size_t boff = (size_t)br * 512 + (k0) + c * 8; \
            uint32_t so = (uint32_t)((r * SMS + c * 8) * 2); \
            cpa16(stb + so,            A + aoff); \
            cpa16(stb + GT_BYTES + so, B + boff); \
        } \
    } while (0)

    G1_LOAD(0, 0);
    CPA_COMMIT();

    for (int ck = 0; ck < 8; ck++) {
        if (ck + 1 < 8) { G1_LOAD((ck + 1) & 1, (ck + 1) * 64); CPA_COMMIT(); CPA_WAIT1(); }
        else            { CPA_WAIT0(); }
        __syncthreads();

        uint32_t stb = sbase + (uint32_t)((ck & 1) * G1_STAGE);
        uint32_t aBase = stb, bBase = stb + GT_BYTES;

#pragma unroll
        for (int ks = 0; ks < 64; ks += 16) {
            uint32_t aoffs = (uint32_t)(((wr * 64 + (lane & 15)) * SMS + ks + ((lane >> 4) << 3)) * 2);
            uint32_t boffs = (uint32_t)(((wc * 32 + ((lane >> 4) << 3) + (lane & 7)) * SMS + ks + (((lane >> 3) & 1) << 3)) * 2);

            uint32_t a_[4][4];
#pragma unroll
            for (int mf = 0; mf < 4; mf++) {
                uint32_t ao = aoffs + (uint32_t)(mf * 16 * SMS * 2);
                ldsm4(a_[mf][0], a_[mf][1], a_[mf][2], a_[mf][3], aBase + ao);
            }
            uint32_t bh[4][2];
#pragma unroll
            for (int np = 0; np < 2; np++) {
                uint32_t bo = boffs + (uint32_t)(np * 16 * SMS * 2);
                ldsm4(bh[np * 2][0], bh[np * 2][1], bh[np * 2 + 1][0], bh[np * 2 + 1][1], bBase + bo);
            }
#pragma unroll
            for (int mf = 0; mf < 4; mf++)
#pragma unroll
                for (int nf = 0; nf < 4; nf++)
                    mma16816h(acc[mf][nf], a_[mf], bh[nf]);
        }
        __syncthreads();
    }
#undef G1_LOAD

#pragma unroll
    for (int mf = 0; mf < 4; mf++) {
#pragma unroll
        for (int nf = 0; nf < 4; nf++) {
            int row0 = rowBase + wr * 64 + mf * 16 + (lane >> 2);
            int col  = colBase + wc * 32 + nf * 8 + 2 * (lane & 3);
            float b0 = bias[col], b1 = bias[col + 1];
#pragma unroll
            for (int half = 0; half < 2; half++) {
                int row = row0 + half * 8;
                if (row < M) {
                    size_t o0 = (size_t)row * N + col;
                    Ch[o0]     = __float2half(acc[mf][nf][half * 2]     + b0);
                    Ch[o0 + 1] = __float2half(acc[mf][nf][half * 2 + 1] + b1);
                }
            }
        }
    }
}

// ---------------- flash attention: 64-q tile, cp.async DB KV, fp16 output ----------------
#define AST 72
#define AT_TILE_BYTES (64 * AST * 2)
#define AT_SCALE 0.18033688f            // 0.125 * log2(e)
__global__ void __launch_bounds__(128) attn_mma_kernel(
    const __half* __restrict__ q, const __half* __restrict__ kvh,
    __half* __restrict__ o)
{
    __shared__ __half sQ[64 * AST];
    __shared__ __half sKV[4 * 64 * AST];

    int tid = threadIdx.x, wid = tid >> 5, lane = tid & 31;
    int bh = blockIdx.y, b = bh >> 3, h = bh & 7;
    int qbase = blockIdx.x * 64;
    size_t qoff = ((size_t)b * NTOK + qbase) * CDIM + h * HD;

#pragma unroll
    for (int i = 0; i < 4; i++) {
        int idx = tid + i * 128;
        int r = idx >> 3, c = (idx & 7) << 3;
        *(uint4*)&sQ[r * AST + c] = *(const uint4*)&q[qoff + (size_t)r * CDIM + c];
    }
    __syncthreads();

    uint32_t bQ   = (uint32_t)__cvta_generic_to_shared(sQ);
    uint32_t kvBs = (uint32_t)__cvta_generic_to_shared(sKV);

    uint32_t qf[4][4];
    {
        uint32_t qrow = (uint32_t)(wid * 16 + (lane & 15));
#pragma unroll
        for (int kt = 0; kt < 4; kt++) {
            uint32_t off = (qrow * AST + kt * 16 + ((lane >> 4) << 3)) * 2;
            ldsm4(qf[kt][0], qf[kt][1], qf[kt][2], qf[kt][3], bQ + off);
        }
    }

    float acc[8][4];
#pragma unroll
    for (int i = 0; i < 8; i++)
#pragma unroll
        for (int j = 0; j < 4; j++) acc[i][j] = 0.f;
    float m0 = -FLT_MAX, m1 = -FLT_MAX, l0 = 0.f, l1 = 0.f;

    size_t kvoff = (size_t)b * NSR * 1024 + h * HD;
    int cbase = 2 * (lane & 3);

#define AT_LOAD(st, kb) do { \
        uint32_t stb = kvBs + (uint32_t)((st) * 2 * AT_TILE_BYTES); \
        _Pragma("unroll") \
        for (int i = 0; i < 4; i++) { \
            int idx = tid + i * 128; \
            int r = idx >> 3, c = (idx & 7) << 3; \
            int gm = (kb) + r; \
            int sz = (gm < NSR) ? 16 : 0; \
            int gmc = (gm < NSR) ? gm : (NSR - 1); \
            const __half* src = kvh + kvoff + (size_t)gmc * 1024 + c; \
            uint32_t so = (uint32_t)((r * AST + c) * 2); \
            cpa16z(stb + so,                 src,       sz); \
            cpa16z(stb + AT_TILE_BYTES + so, src + 512, sz); \
        } \
    } while (0)

    AT_LOAD(0, 0);
    CPA_COMMIT();

    for (int it = 0; it < 16; it++) {
        if (it + 1 < 16) { AT_LOAD((it + 1) & 1, (it + 1) * 64); CPA_COMMIT(); CPA_WAIT1(); }
        else             { CPA_WAIT0(); }
        __syncthreads();

        uint32_t stb = kvBs + (uint32_t)((it & 1) * 2 * AT_TILE_BYTES);
        uint32_t bK = stb, bV = stb + AT_TILE_BYTES;
        int kb = it * 64;

        float s_[8][4];
#pragma unroll
        for (int i = 0; i < 8; i++)
#pragma unroll
            for (int j = 0; j < 4; j++) s_[i][j] = 0.f;

#pragma unroll
        for (int kt = 0; kt < 4; kt++) {
#pragma unroll
            for (int np = 0; np < 4; np++) {
                uint32_t brow = (uint32_t)(np * 16 + ((lane >> 4) << 3) + (lane & 7));
                uint32_t boff = (brow * AST + kt * 16 + (((lane >> 3) & 1) << 3)) * 2;
                uint32_t h0, h1, h2, h3;
                ldsm4(h0, h1, h2, h3, bK + boff);
                uint32_t fh0[2] = {h0, h1}, fh1[2] = {h2, h3};
                mma16816h(s_[np * 2],     qf[kt], fh0);
                mma16816h(s_[np * 2 + 1], qf[kt], fh1);
            }
        }

        int valid = NSR - kb; if (valid > 64) valid = 64;
        float rm0 = -FLT_MAX, rm1 = -FLT_MAX;
#pragma unroll
        for (int nt = 0; nt < 8; nt++) {
#pragma unroll
            for (int j = 0; j < 4; j++) s_[nt][j] *= AT_SCALE;
            rm0 = fmaxf(rm0, fmaxf(s_[nt][0], s_[nt][1]));
            rm1 = fmaxf(rm1, fmaxf(s_[nt][2], s_[nt][3]));
        }
        rm0 = fmaxf(rm0, __shfl_xor_sync(0xffffffffu, rm0, 1));
        rm0 = fmaxf(rm0, __shfl_xor_sync(0xffffffffu, rm0, 2));
        rm1 = fmaxf(rm1, __shfl_xor_sync(0xffffffffu, rm1, 1));
        rm1 = fmaxf(rm1, __shfl_xor_sync(0xffffffffu, rm1, 2));
        float nm0 = fmaxf(m0, rm0), nm1 = fmaxf(m1, rm1);
        float corr0 = exp2f(m0 - nm0), corr1 = exp2f(m1 - nm1);
        m0 = nm0; m1 = nm1;

        float sum0 = 0.f, sum1 = 0.f;
#pragma unroll
        for (int nt = 0; nt < 8; nt++) {
            int c0 = nt * 8 + cbase;
            float p0 = (c0     < valid) ? exp2f(s_[nt][0] - nm0) : 0.f;
            float p1 = (c0 + 1 < valid) ? exp2f(s_[nt][1] - nm0) : 0.f;
            float p2 = (c0     < valid) ? exp2f(s_[nt][2] - nm1) : 0.f;
            float p3 = (c0 + 1 < valid) ? exp2f(s_[nt][3] - nm1) : 0.f;
            sum0 += p0 + p1; sum1 += p2 + p3;
            s_[nt][0] = p0; s_[nt][1] = p1; s_[nt][2] = p2; s_[nt][3] = p3;
        }
        sum0 += __shfl_xor_sync(0xffffffffu, sum0, 1);
        sum0 += __shfl_xor_sync(0xffffffffu, sum0, 2);
        sum1 += __shfl_xor_sync(0xffffffffu, sum1, 1);
        sum1 += __shfl_xor_sync(0xffffffffu, sum1, 2);
        l0 = l0 * corr0 + sum0;
        l1 = l1 * corr1 + sum1;

#pragma unroll
        for (int nt = 0; nt < 8; nt++) {
            acc[nt][0] *= corr0; acc[nt][1] *= corr0;
            acc[nt][2] *= corr1; acc[nt][3] *= corr1;
        }

#pragma unroll
        for (int kt = 0; kt < 4; kt++) {
            uint32_t ph[4];
#pragma unroll
            for (int q2 = 0; q2 < 2; q2++) {
                int nt = 2 * kt + q2;
                ph[q2 * 2]     = packh2(s_[nt][0], s_[nt][1]);
                ph[q2 * 2 + 1] = packh2(s_[nt][2], s_[nt][3]);
            }
            int l8 = lane >> 3, li = lane & 7;
#pragma unroll
            for (int np = 0; np < 4; np++) {
                uint32_t vrow = (uint32_t)(kt * 16 + ((l8 & 1) << 3) + li);
                uint32_t vcol = (uint32_t)(np * 16 + ((l8 >> 1) << 3));
                uint32_t voff = (vrow * AST + vcol) * 2;
                uint32_t h0, h1, h2, h3;
                ldsm4t(h0, h1, h2, h3, bV + voff);
                uint32_t fh0[2] = {h0, h1}, fh1[2] = {h2, h3};
                mma16816h(acc[np * 2],     ph, fh0);
                mma16816h(acc[np * 2 + 1], ph, fh1);
            }
        }
        __syncthreads();
    }
#undef AT_LOAD

    float inv0 = 1.f / l0, inv1 = 1.f / l1;
    int r0 = qbase + wid * 16 + (lane >> 2);
    size_t ob0 = ((size_t)b * NTOK + r0) * CDIM + h * HD;
    size_t ob1 = ob0 + (size_t)8 * CDIM;
#pragma unroll
    for (int nt = 0; nt < 8; nt++) {
        int cc = nt * 8 + cbase;
        *(uint32_t*)&o[ob0 + cc] = packh2(acc[nt][0] * inv0, acc[nt][1] * inv0);
        *(uint32_t*)&o[ob1 + cc] = packh2(acc[nt][2] * inv1, acc[nt][3] * inv1);
    }
}

// ---------------- trilinear upsample of V(fp16) + LN + add o(fp16) -> fp16 hi/lo ----------------
__global__ void __launch_bounds__(256) ups_ln_add_kernel(
    const __half* __restrict__ kvh, const __half* __restrict__ ob,
    const float* __restrict__ g, const float* __restrict__ beta,
    __half* __restrict__ yh, __half* __restrict__ yl)
{
    int bn = blockIdx.x;
    int b = bn / NTOK, n = bn % NTOK;
    int d = n / 400, hh = (n / 20) % 20, ww = n % 20;
    float sd = d  * 0.5f - 0.25f; int fd = (int)floorf(sd); float wdz = sd - (float)fd;
    float sh = hh * 0.5f - 0.25f; int fh = (int)floorf(sh); float why = sh - (float)fh;
    float sw = ww * 0.5f - 0.25f; int fw = (int)floorf(sw); float wwx = sw - (float)fw;
    int dz0 = fd < 0 ? 0 : fd; int dz1 = (fd + 1) > 9 ? 9 : (fd + 1);
    int hy0 = fh < 0 ? 0 : fh; int hy1 = (fh + 1) > 9 ? 9 : (fh + 1);
    int wx0 = fw < 0 ? 0 : fw; int wx1 = (fw + 1) > 9 ? 9 : (fw + 1);
    int midx[8]; float wt8[8];
    {
        int zz[2] = {dz0, dz1};  float wz[2] = {1.f - wdz, wdz};
        int yy[2] = {hy0, hy1};  float wy[2] = {1.f - why, why};
        int xx[2] = {wx0, wx1};  float wx[2] = {1.f - wwx, wwx};
        int t = 0;
        for (int a = 0; a < 2; a++)
            for (int b2 = 0; b2 < 2; b2++)
                for (int c2 = 0; c2 < 2; c2++) {
                    midx[t] = zz[a] * 100 + yy[b2] * 10 + xx[c2];
                    wt8[t]  = wz[a] * wy[b2] * wx[c2]; t++;
                }
    }
    __shared__ float vals[CDIM];
    __shared__ float red[18];
    size_t kvb = (size_t)b * NSR * 1024 + 512;   // V half of fp16 kv
    float loc[2];
#pragma unroll
    for (int ci = 0; ci < 2; ci++) {
        int c = threadIdx.x + ci * 256;
        float acc = 0.f;
#pragma unroll
        for (int t = 0; t < 8; t++)
            acc += wt8[t] * __half2float(kvh[kvb + (size_t)midx[t] * 1024 + c]);
        vals[c] = acc; loc[ci] = acc;
    }
    float s = loc[0] + loc[1], sq = loc[0] * loc[0] + loc[1] * loc[1];
#pragma unroll
    for (int o2 = 16; o2 > 0; o2 >>= 1) {
        s  += __shfl_down_sync(0xffffffffu, s,  o2);
        sq += __shfl_down_sync(0xffffffffu, sq, o2);
    }
    int w = threadIdx.x >> 5;
    if ((threadIdx.x & 31) == 0) { red[w] = s; red[8 + w] = sq; }
    __syncthreads();
    if (threadIdx.x == 0) {
        float a = 0.f, b2 = 0.f;
        for (int i = 0; i < 8; i++) { a += red[i]; b2 += red[8 + i]; }
        red[16] = a; red[17] = b2;
    }
    __syncthreads();
    float mean = red[16] * (1.f / CDIM);
    float var  = red[17] * (1.f / CDIM) - mean * mean;
    float inv  = rsqrtf(var + 1e-6f);
#pragma unroll
    for (int ci = 0; ci < 2; ci++) {
        int c = threadIdx.x + ci * 256;
        size_t oidx = ((size_t)b * NTOK + n) * CDIM + c;
        float v = __half2float(ob[oidx]) + (vals[c] - mean) * inv * g[c] + beta[c];
        __half hb = __float2half(v);
        yh[oidx] = hb;
        yl[oidx] = __float2half(v - __half2float(hb));
    }
}

// ---------------- launch ----------------
extern "C" void kernel_launch(void* const* d_in, const int* in_sizes, int n_in,
                              void* d_out, int out_size)
{
    const float* x      = (const float*)d_in[0];
    const float* Wq     = (const float*)d_in[1];
    const float* bq     = (const float*)d_in[2];
    const float* Wkv    = (const float*)d_in[3];
    const float* bkv    = (const float*)d_in[4];
    const float* srw    = (const float*)d_in[5];
    const float* srb    = (const float*)d_in[6];
    const float* srg    = (const float*)d_in[7];
    const float* srbeta = (const float*)d_in[8];
    const float* upg    = (const float*)d_in[9];
    const float* upbeta = (const float*)d_in[10];
    const float* Wp     = (const float*)d_in[11];
    const float* bp     = (const float*)d_in[12];
    float* out = (float*)d_out;

    __half *oh, *xh, *yh, *yl, *xrh, *xrl, *qh, *kvh, *wqt, *wkvt, *wpt;
    cudaGetSymbolAddress((void**)&oh,  g_oh);
    cudaGetSymbolAddress((void**)&xh,  g_xh);
    cudaGetSymbolAddress((void**)&yh,  g_yh);
    cudaGetSymbolAddress((void**)&yl,  g_yl);
    cudaGetSymbolAddress((void**)&qh,  g_qh);
    cudaGetSymbolAddress((void**)&kvh, g_kvh);
    cudaGetSymbolAddress((void**)&xrh, g_xrh);
    cudaGetSymbolAddress((void**)&xrl, g_xrl);
    cudaGetSymbolAddress((void**)&wqt, g_wqt);
    cudaGetSymbolAddress((void**)&wkvt, g_wkvt);
    cudaGetSymbolAddress((void**)&wpt, g_wpt);

    cudaFuncSetAttribute(gemm2h_kernel, cudaFuncAttributeMaxDynamicSharedMemorySize, G2_SMEM);
    cudaFuncSetAttribute(gemm1h_kernel, cudaFuncAttributeMaxDynamicSharedMemorySize, G1_SMEM);

    // 1. merged pre-pass: weight transpose + x->fp16 + conv/LN
    pre_kernel<<<PRE_WSPLIT + PRE_CVT + PRE_CONV, 256>>>(
        Wq, Wkv, Wp, wqt, wkvt, wpt, x, xh, srw, srb, srg, srbeta, xrh, xrl);

    // 2. kv = xr @ Wkv + bkv -> fp16 only
    gemm2h_kernel<<<dim3(1024 / 128, (BATCH * NSR + 127) / 128), 256, G2_SMEM>>>(
        xrh, xrl, wkvt, bkv, (float*)nullptr, kvh, BATCH * NSR, 1024);
    // 3. q = xh @ Wq + bq -> fp16
    gemm1h_kernel<<<dim3(512 / 128, (BATCH * NTOK) / 128), 256, G1_SMEM>>>(
        xh, wqt, bq, qh, BATCH * NTOK, 512);

    // 4. attention
    attn_mma_kernel<<<dim3(NTOK / 64, BATCH * NHEADS), 128>>>(qh, kvh, oh);

    // 5. upsample(V fp16) + LN + add o
    ups_ln_add_kernel<<<BATCH * NTOK, 256>>>(kvh, oh, upg, upbeta, yh, yl);

    // 6. out = (yh+yl) @ Wp + bp -> f32
    gemm2h_kernel<<<dim3(512 / 128, (BATCH * NTOK) / 128), 256, G2_SMEM>>>(
        yh, yl, wpt, bp, out, (__half*)nullptr, BATCH * NTOK, 512);
}